// round 1
// baseline (speedup 1.0000x reference)
#include <cuda_runtime.h>
#include <math.h>

#define Bsz 2
#define Tn  1024
#define Dm  1024
#define Hn  16
#define DHn 64
#define BHn (Bsz*Hn)
#define MAXP 64

// ---------------- scratch (static device arrays; no allocation) ----------------
__device__ float g_Q[BHn*Tn*DHn];            // (b,h,t,dh)  8MB
__device__ float g_K[BHn*Tn*DHn];            // 8MB
__device__ float g_V[BHn*Tn*DHn];            // 8MB
__device__ float g_QPE[BHn*Tn*MAXP];         // (b,h,t,p)   8MB
__device__ float g_S[(long)BHn*Tn*Tn];       // scores -> probs, 128MB
__device__ float g_AO[Bsz*Tn*Dm];            // (b,t,d)     8MB

// ---------------- generic NT SGEMM: C = A * B^T (+bias), 128x128x8 ----------------
// mode 0: C[m*N+n] plain.  mode 1: scatter (b,t)x(h,dh) -> (b,h,t,dh).
// causal: skip blocks with bn >= bm+128 (keeps diagonal blocks).
__global__ __launch_bounds__(256) void sgemm128(
    const float* __restrict__ A, const float* __restrict__ Bm,
    const float* __restrict__ bias, float* __restrict__ C,
    int M, int N, int K,
    long sA, long sB, long sC, int mode, int causal)
{
    const int z = blockIdx.z;
    A  += (long)z * sA;
    Bm += (long)z * sB;
    C  += (long)z * sC;
    const int bm = blockIdx.y * 128;
    const int bn = blockIdx.x * 128;
    if (causal && bn >= bm + 128) return;

    __shared__ float As[8][132];
    __shared__ float Bs[8][132];

    const int tid = threadIdx.x;
    const int lr  = tid >> 1;
    const int lk  = (tid & 1) << 2;
    const int tx  = tid & 15;
    const int ty  = tid >> 4;

    float acc[8][8];
#pragma unroll
    for (int i = 0; i < 8; i++)
#pragma unroll
        for (int j = 0; j < 8; j++) acc[i][j] = 0.f;

    const float* Ap = A + (long)(bm + lr) * K + lk;
    const float* Bp = Bm + (long)(bn + lr) * K + lk;

    for (int k0 = 0; k0 < K; k0 += 8) {
        float4 a4 = *(const float4*)(Ap + k0);
        float4 b4 = *(const float4*)(Bp + k0);
        __syncthreads();
        As[lk + 0][lr] = a4.x; As[lk + 1][lr] = a4.y;
        As[lk + 2][lr] = a4.z; As[lk + 3][lr] = a4.w;
        Bs[lk + 0][lr] = b4.x; Bs[lk + 1][lr] = b4.y;
        Bs[lk + 2][lr] = b4.z; Bs[lk + 3][lr] = b4.w;
        __syncthreads();
#pragma unroll
        for (int kk = 0; kk < 8; kk++) {
            float4 a0 = *(const float4*)&As[kk][ty * 8];
            float4 a1 = *(const float4*)&As[kk][ty * 8 + 4];
            float4 b0 = *(const float4*)&Bs[kk][tx * 8];
            float4 b1 = *(const float4*)&Bs[kk][tx * 8 + 4];
            float av[8] = {a0.x, a0.y, a0.z, a0.w, a1.x, a1.y, a1.z, a1.w};
            float bv[8] = {b0.x, b0.y, b0.z, b0.w, b1.x, b1.y, b1.z, b1.w};
#pragma unroll
            for (int i = 0; i < 8; i++)
#pragma unroll
                for (int j = 0; j < 8; j++)
                    acc[i][j] = fmaf(av[i], bv[j], acc[i][j]);
        }
    }

    const int n0 = bn + tx * 8;
    if (mode == 0) {
#pragma unroll
        for (int ii = 0; ii < 8; ii++) {
            const int m = bm + ty * 8 + ii;
            float* cp = C + (long)m * N + n0;
#pragma unroll
            for (int jj = 0; jj < 8; jj++) {
                float b_ = bias ? bias[n0 + jj] : 0.f;
                cp[jj] = acc[ii][jj] + b_;
            }
        }
    } else {
        const int h = n0 >> 6, dh0 = n0 & 63;
#pragma unroll
        for (int ii = 0; ii < 8; ii++) {
            const int m = bm + ty * 8 + ii;
            const int b = m >> 10, t = m & 1023;
            float* cp = C + (((long)(b * Hn + h) * Tn + t) * DHn) + dh0;
#pragma unroll
            for (int jj = 0; jj < 8; jj++) {
                float b_ = bias ? bias[n0 + jj] : 0.f;
                cp[jj] = acc[ii][jj] + b_;
            }
        }
    }
}

// ---------------- qpe table: QPE[b,h,i,p] = sum_d Q[b,h,i,d] * pe[h,p,d] ----------------
// grid (Tn/64, BH), 256 threads, 64x64 tile, K=64 in one shot.
__global__ __launch_bounds__(256) void qpe_kernel(const float* __restrict__ PE,
                                                  const float* __restrict__ Q,
                                                  float* __restrict__ QPE)
{
    const int it = blockIdx.x, bh = blockIdx.y, h = bh & (Hn - 1);
    const float* Aq = Q + ((long)bh * Tn + it * 64) * DHn;
    const float* Bp = PE + (long)h * MAXP * DHn;

    __shared__ float Qs[64][65];
    __shared__ float Ps[64][65];

    const int tid = threadIdx.x;
    const int rowb = tid >> 4, c4 = (tid & 15) << 2;
#pragma unroll
    for (int r = 0; r < 4; r++) {
        int row = rowb + r * 16;
        float4 q4 = *(const float4*)(Aq + (long)row * DHn + c4);
        Qs[row][c4] = q4.x; Qs[row][c4 + 1] = q4.y;
        Qs[row][c4 + 2] = q4.z; Qs[row][c4 + 3] = q4.w;
        float4 p4 = *(const float4*)(Bp + (long)row * DHn + c4);
        Ps[row][c4] = p4.x; Ps[row][c4 + 1] = p4.y;
        Ps[row][c4 + 2] = p4.z; Ps[row][c4 + 3] = p4.w;
    }
    __syncthreads();

    const int tx = tid & 15, ty = tid >> 4;
    float acc[4][4];
#pragma unroll
    for (int i = 0; i < 4; i++)
#pragma unroll
        for (int j = 0; j < 4; j++) acc[i][j] = 0.f;

#pragma unroll 16
    for (int kk = 0; kk < 64; kk++) {
        float a0 = Qs[ty * 4 + 0][kk], a1 = Qs[ty * 4 + 1][kk];
        float a2 = Qs[ty * 4 + 2][kk], a3 = Qs[ty * 4 + 3][kk];
        float b0 = Ps[tx * 4 + 0][kk], b1 = Ps[tx * 4 + 1][kk];
        float b2 = Ps[tx * 4 + 2][kk], b3 = Ps[tx * 4 + 3][kk];
        acc[0][0] = fmaf(a0, b0, acc[0][0]); acc[0][1] = fmaf(a0, b1, acc[0][1]);
        acc[0][2] = fmaf(a0, b2, acc[0][2]); acc[0][3] = fmaf(a0, b3, acc[0][3]);
        acc[1][0] = fmaf(a1, b0, acc[1][0]); acc[1][1] = fmaf(a1, b1, acc[1][1]);
        acc[1][2] = fmaf(a1, b2, acc[1][2]); acc[1][3] = fmaf(a1, b3, acc[1][3]);
        acc[2][0] = fmaf(a2, b0, acc[2][0]); acc[2][1] = fmaf(a2, b1, acc[2][1]);
        acc[2][2] = fmaf(a2, b2, acc[2][2]); acc[2][3] = fmaf(a2, b3, acc[2][3]);
        acc[3][0] = fmaf(a3, b0, acc[3][0]); acc[3][1] = fmaf(a3, b1, acc[3][1]);
        acc[3][2] = fmaf(a3, b2, acc[3][2]); acc[3][3] = fmaf(a3, b3, acc[3][3]);
    }

    float* out = QPE + ((long)bh * Tn + it * 64) * MAXP;
#pragma unroll
    for (int ii = 0; ii < 4; ii++) {
        float4 o4 = make_float4(acc[ii][0], acc[ii][1], acc[ii][2], acc[ii][3]);
        *(float4*)(out + (long)(ty * 4 + ii) * MAXP + tx * 4) = o4;
    }
}

// ---------------- CoPE gates + suffix-cumsum + interp + softmax (in-place on g_S row) ----------
// grid (Tn, BH), 256 threads; each thread owns 4 contiguous j.
__global__ __launch_bounds__(256) void cope_kernel(float* __restrict__ S,
                                                   const float* __restrict__ QPE)
{
    const int i = blockIdx.x, bh = blockIdx.y;
    float* row = S + ((long)bh * Tn + i) * Tn;
    const float* qpe = QPE + ((long)bh * Tn + i) * MAXP;

    __shared__ float qpes[64];
    __shared__ float wred[8];
    __shared__ float wred2[8];

    const int tid = threadIdx.x, lane = tid & 31, wid = tid >> 5;
    if (tid < 64) qpes[tid] = qpe[tid];

    const int j0 = tid << 2;
    float4 s4 = *(const float4*)(row + j0);
    float qk[4] = {s4.x, s4.y, s4.z, s4.w};

    float lpre[4];
    float run = 0.f;
#pragma unroll
    for (int q = 0; q < 4; q++) {
        float gg = 0.f;
        if (j0 + q <= i)
            gg = __fdividef(1.f, 1.f + __expf(-0.125f * qk[q]));
        run += gg;
        lpre[q] = run;
    }

    // block inclusive scan of per-thread sums
    float v = run;
#pragma unroll
    for (int o = 1; o < 32; o <<= 1) {
        float t = __shfl_up_sync(0xffffffffu, v, o);
        if (lane >= o) v += t;
    }
    if (lane == 31) wred[wid] = v;
    __syncthreads();
    if (tid < 8) {
        float w = wred[tid];
#pragma unroll
        for (int o = 1; o < 8; o <<= 1) {
            float t = __shfl_up_sync(0x000000ffu, w, o);
            if (tid >= o) w += t;
        }
        wred[tid] = w;
    }
    __syncthreads();
    const float base  = (v - run) + (wid ? wred[wid - 1] : 0.f);
    const float total = wred[7];

    float sc[4];
    float mx = -INFINITY;
#pragma unroll
    for (int q = 0; q < 4; q++) {
        float s_ = -INFINITY;
        if (j0 + q <= i) {
            float pos = total - (base + lpre[q]);
            pos = fminf(fmaxf(pos, 0.f), 63.f);
            float pf = floorf(pos);
            int fi = (int)pf;
            float al = pos - pf;
            int ci = (fi < 63) ? fi + 1 : 63;
            float qf = qpes[fi], qc = qpes[ci];
            float qv = qf + al * (qc - qf);
            s_ = 0.125f * (qk[q] + qv);
        }
        sc[q] = s_;
        mx = fmaxf(mx, s_);
    }
#pragma unroll
    for (int o = 16; o; o >>= 1) mx = fmaxf(mx, __shfl_xor_sync(0xffffffffu, mx, o));
    if (lane == 0) wred2[wid] = mx;
    __syncthreads();
    float bmax = wred2[0];
#pragma unroll
    for (int k = 1; k < 8; k++) bmax = fmaxf(bmax, wred2[k]);

    float p[4];
    float ssum = 0.f;
#pragma unroll
    for (int q = 0; q < 4; q++) {
        float e = (j0 + q <= i) ? __expf(sc[q] - bmax) : 0.f;
        p[q] = e;
        ssum += e;
    }
#pragma unroll
    for (int o = 16; o; o >>= 1) ssum += __shfl_xor_sync(0xffffffffu, ssum, o);
    __syncthreads();              // done reading wred2 as maxes
    if (lane == 0) wred2[wid] = ssum;
    __syncthreads();
    float tot = 0.f;
#pragma unroll
    for (int k = 0; k < 8; k++) tot += wred2[k];
    const float inv = __fdividef(1.f, tot);

    float4 o4 = make_float4(p[0] * inv, p[1] * inv, p[2] * inv, p[3] * inv);
    *(float4*)(row + j0) = o4;
}

// ---------------- AO[b,t,(h,dh)] = sum_j P[i,j] * V[b,h,j,dh] ----------------
// grid (Tn/64, BH), 256 threads, 64 i x 64 dh tile, causal-limited k loop.
__global__ __launch_bounds__(256) void pv_kernel(const float* __restrict__ S,
                                                 const float* __restrict__ V,
                                                 float* __restrict__ AO)
{
    const int it = blockIdx.x, bh = blockIdx.y;
    const int b = bh >> 4, h = bh & 15;
    const float* Pr = S + ((long)bh * Tn + it * 64) * Tn;
    const float* Vr = V + (long)bh * Tn * DHn;

    __shared__ float Ps[64][65];
    __shared__ float Vs[64][68];

    const int tid = threadIdx.x;
    const int tx = tid & 15, ty = tid >> 4;
    const int rowb = tid >> 4, c4 = (tid & 15) << 2;

    float acc[4][4];
#pragma unroll
    for (int i = 0; i < 4; i++)
#pragma unroll
        for (int j = 0; j < 4; j++) acc[i][j] = 0.f;

    const int kend = it * 64 + 64;   // probs are exactly 0 for j > i
    for (int k0 = 0; k0 < kend; k0 += 64) {
        __syncthreads();
#pragma unroll
        for (int r = 0; r < 4; r++) {
            int row = rowb + r * 16;
            float4 p4 = *(const float4*)(Pr + (long)row * Tn + k0 + c4);
            Ps[row][c4] = p4.x; Ps[row][c4 + 1] = p4.y;
            Ps[row][c4 + 2] = p4.z; Ps[row][c4 + 3] = p4.w;
            float4 v4 = *(const float4*)(Vr + (long)(k0 + row) * DHn + c4);
            *(float4*)&Vs[row][c4] = v4;
        }
        __syncthreads();
#pragma unroll 8
        for (int kk = 0; kk < 64; kk++) {
            float4 bv = *(const float4*)&Vs[kk][tx * 4];
#pragma unroll
            for (int ii = 0; ii < 4; ii++) {
                float a = Ps[ty * 4 + ii][kk];
                acc[ii][0] = fmaf(a, bv.x, acc[ii][0]);
                acc[ii][1] = fmaf(a, bv.y, acc[ii][1]);
                acc[ii][2] = fmaf(a, bv.z, acc[ii][2]);
                acc[ii][3] = fmaf(a, bv.w, acc[ii][3]);
            }
        }
    }

    float* out = AO + ((long)b * Tn + it * 64) * Dm + h * DHn;
#pragma unroll
    for (int ii = 0; ii < 4; ii++) {
        float4 o4 = make_float4(acc[ii][0], acc[ii][1], acc[ii][2], acc[ii][3]);
        *(float4*)(out + (long)(ty * 4 + ii) * Dm + tx * 4) = o4;
    }
}

// ---------------- launcher ----------------
extern "C" void kernel_launch(void* const* d_in, const int* in_sizes, int n_in,
                              void* d_out, int out_size)
{
    (void)in_sizes; (void)n_in; (void)out_size;
    const float* x  = (const float*)d_in[0];
    const float* Wq = (const float*)d_in[1];
    const float* bq = (const float*)d_in[2];
    const float* Wk = (const float*)d_in[3];
    const float* bk = (const float*)d_in[4];
    const float* Wv = (const float*)d_in[5];
    const float* bv = (const float*)d_in[6];
    const float* Wo = (const float*)d_in[7];
    const float* bo = (const float*)d_in[8];
    const float* pe = (const float*)d_in[9];
    float* out = (float*)d_out;

    float *Qd, *Kd, *Vd, *Sd, *QPEd, *AOd;
    cudaGetSymbolAddress((void**)&Qd, g_Q);
    cudaGetSymbolAddress((void**)&Kd, g_K);
    cudaGetSymbolAddress((void**)&Vd, g_V);
    cudaGetSymbolAddress((void**)&Sd, g_S);
    cudaGetSymbolAddress((void**)&QPEd, g_QPE);
    cudaGetSymbolAddress((void**)&AOd, g_AO);

    dim3 blk(256);

    // QKV projections: (2048,1024) @ (1024,1024)^T, scatter to (b,h,t,dh)
    sgemm128<<<dim3(8, 16, 1), blk>>>(x, Wq, bq, Qd, 2048, 1024, 1024, 0, 0, 0, 1, 0);
    sgemm128<<<dim3(8, 16, 1), blk>>>(x, Wk, bk, Kd, 2048, 1024, 1024, 0, 0, 0, 1, 0);
    sgemm128<<<dim3(8, 16, 1), blk>>>(x, Wv, bv, Vd, 2048, 1024, 1024, 0, 0, 0, 1, 0);

    // qk = Q @ K^T per (b,h), causal block skip
    sgemm128<<<dim3(8, 8, 32), blk>>>(Qd, Kd, nullptr, Sd, 1024, 1024, 64,
                                      (long)Tn * DHn, (long)Tn * DHn, (long)Tn * Tn, 0, 1);

    // qpe table
    qpe_kernel<<<dim3(16, 32), blk>>>(pe, Qd, QPEd);

    // gates + suffix cumsum + interp + softmax (in place on S)
    cope_kernel<<<dim3(1024, 32), blk>>>(Sd, QPEd);

    // attn @ V
    pv_kernel<<<dim3(16, 32), blk>>>(Sd, Vd, AOd);

    // output projection
    sgemm128<<<dim3(8, 16, 1), blk>>>(AOd, Wo, bo, out, 2048, 1024, 1024, 0, 0, 0, 0, 0);
}

// round 3
// speedup vs baseline: 1.9198x; 1.9198x over previous
#include <cuda_runtime.h>
#include <cuda_bf16.h>
#include <math.h>
#include <stdint.h>

#define Bsz 2
#define Tn  1024
#define Dm  1024
#define Hn  16
#define DHn 64
#define BHn (Bsz*Hn)
#define MAXP 64

// ---------------- scratch (static device arrays; no allocation) ----------------
__device__ float g_Qf[BHn*Tn*DHn];           // fp32 Q (for qpe)
__device__ float g_Vf[BHn*Tn*DHn];           // fp32 V (for pv)
__device__ float g_QPE[BHn*Tn*MAXP];
__device__ float g_S[(long)BHn*Tn*Tn];       // scores -> probs, 128MB
__device__ float g_AO[Bsz*Tn*Dm];
__device__ __nv_bfloat16 g_xh[Bsz*Tn*Dm],  g_xl[Bsz*Tn*Dm];
__device__ __nv_bfloat16 g_Wqh[Dm*Dm], g_Wql[Dm*Dm];
__device__ __nv_bfloat16 g_Wkh[Dm*Dm], g_Wkl[Dm*Dm];
__device__ __nv_bfloat16 g_Wvh[Dm*Dm], g_Wvl[Dm*Dm];
__device__ __nv_bfloat16 g_Woh[Dm*Dm], g_Wol[Dm*Dm];
__device__ __nv_bfloat16 g_Qh[BHn*Tn*DHn], g_Ql[BHn*Tn*DHn];
__device__ __nv_bfloat16 g_Kh[BHn*Tn*DHn], g_Kl[BHn*Tn*DHn];
__device__ __nv_bfloat16 g_AOh[Bsz*Tn*Dm], g_AOl[Bsz*Tn*Dm];

// ---------------- helpers ----------------
__device__ __forceinline__ uint32_t smem_u32(const void* p) {
    uint32_t a;
    asm("{ .reg .u64 t; cvta.to.shared.u64 t, %1; cvt.u32.u64 %0, t; }" : "=r"(a) : "l"(p));
    return a;
}
__device__ __forceinline__ void cpa16(uint32_t dst, const void* src) {
    asm volatile("cp.async.cg.shared.global [%0], [%1], 16;" :: "r"(dst), "l"(src));
}
#define CPA_COMMIT() asm volatile("cp.async.commit_group;" ::: "memory")
#define CPA_WAIT2()  asm volatile("cp.async.wait_group 2;" ::: "memory")

#define LDSM4(r, a) \
    asm volatile("ldmatrix.sync.aligned.m8n8.x4.shared.b16 {%0,%1,%2,%3}, [%4];" \
        : "=r"((r)[0]), "=r"((r)[1]), "=r"((r)[2]), "=r"((r)[3]) : "r"(a))

#define MMA_BF16(c, a, b0v, b1v) \
    asm volatile("mma.sync.aligned.m16n8k16.row.col.f32.bf16.bf16.f32 " \
        "{%0,%1,%2,%3},{%4,%5,%6,%7},{%8,%9},{%0,%1,%2,%3};" \
        : "+f"((c)[0]), "+f"((c)[1]), "+f"((c)[2]), "+f"((c)[3]) \
        : "r"((a)[0]), "r"((a)[1]), "r"((a)[2]), "r"((a)[3]), "r"(b0v), "r"(b1v))

// ---------------- split fp32 -> bf16 hi/lo ----------------
__global__ __launch_bounds__(256) void splitk(const float* __restrict__ s,
                                              __nv_bfloat16* __restrict__ h,
                                              __nv_bfloat16* __restrict__ l, int n)
{
    int i = (blockIdx.x * 256 + threadIdx.x) * 4;
    if (i >= n) return;
    float4 v = *(const float4*)(s + i);
    __nv_bfloat16 h0 = __float2bfloat16(v.x), h1 = __float2bfloat16(v.y);
    __nv_bfloat16 h2 = __float2bfloat16(v.z), h3 = __float2bfloat16(v.w);
    __nv_bfloat16 l0 = __float2bfloat16(v.x - __bfloat162float(h0));
    __nv_bfloat16 l1 = __float2bfloat16(v.y - __bfloat162float(h1));
    __nv_bfloat16 l2 = __float2bfloat16(v.z - __bfloat162float(h2));
    __nv_bfloat16 l3 = __float2bfloat16(v.w - __bfloat162float(h3));
    __nv_bfloat162 H0; H0.x = h0; H0.y = h1;
    __nv_bfloat162 H1; H1.x = h2; H1.y = h3;
    __nv_bfloat162 L0; L0.x = l0; L0.y = l1;
    __nv_bfloat162 L1; L1.x = l2; L1.y = l3;
    *(__nv_bfloat162*)(h + i)     = H0;
    *(__nv_bfloat162*)(h + i + 2) = H1;
    *(__nv_bfloat162*)(l + i)     = L0;
    *(__nv_bfloat162*)(l + i + 2) = L1;
}

// ---------------- HMMA split-bf16 GEMM: C = (Ahi+Alo)(Bhi+Blo)^T + bias --------
// BM=BN=128, BK=32, 256 threads (2x4 warps, warp tile 64x32), NS=3 cp.async stages.
// smem stage layout: [Ah 128x40bf16][Al][Bh][Bl], rows padded to 80B (bank-clean
// ldmatrix: 20*r mod 32 distinct for r=0..7).
#define NS   3
#define PITCH 80        // bytes per row (64 data + 16 pad)
#define MATB (128*PITCH)     // 10240 bytes per matrix
#define STG  (4*MATB)        // 40960 per stage
#define MM_SMEM (NS*STG)     // 122880

__global__ __launch_bounds__(256, 1) void mm_hmma(
    const __nv_bfloat16* __restrict__ Ahi, const __nv_bfloat16* __restrict__ Alo,
    const __nv_bfloat16* __restrict__ Bhi, const __nv_bfloat16* __restrict__ Blo,
    const float* __restrict__ bias,
    float* __restrict__ Cf, __nv_bfloat16* __restrict__ Ch, __nv_bfloat16* __restrict__ Cl,
    int M, int N, int K, long sA, long sB, long sC, int scatter, int causal)
{
    if (causal && blockIdx.x > blockIdx.y) return;

    extern __shared__ char dsm[];
    const uint32_t sbase = smem_u32(dsm);

    const int tid  = threadIdx.x;
    const int wid  = tid >> 5;
    const int lane = tid & 31;
    const int wm   = wid & 1;      // 0..1  -> 64 rows each
    const int wn   = wid >> 1;     // 0..3  -> 32 cols each
    const int z    = blockIdx.z;
    const int bm   = blockIdx.y * 128;
    const int bn   = blockIdx.x * 128;

    const __nv_bfloat16* Ah = Ahi + (long)z * sA + (long)bm * K;
    const __nv_bfloat16* Al = Alo + (long)z * sA + (long)bm * K;
    const __nv_bfloat16* Bh = Bhi + (long)z * sB + (long)bn * K;
    const __nv_bfloat16* Bl = Blo + (long)z * sB + (long)bn * K;

    float acc[4][4][4];
#pragma unroll
    for (int i = 0; i < 4; i++)
#pragma unroll
        for (int j = 0; j < 4; j++)
#pragma unroll
            for (int c = 0; c < 4; c++) acc[i][j][c] = 0.f;

    const int KS = K >> 5;   // K/32 iterations

    // 512 16B-chunks per matrix per stage; each thread does 2 chunks x 4 matrices
    auto load_stage = [&](int slot, int ks) {
        const uint32_t base = sbase + slot * STG;
        const int k0 = ks * 32;
#pragma unroll
        for (int c = tid; c < 512; c += 256) {
            const int r = c >> 2, seg = c & 3;
            const uint32_t d = base + r * PITCH + seg * 16;
            const long off = (long)r * K + k0 + seg * 8;
            cpa16(d,            Ah + off);
            cpa16(d + MATB,     Al + off);
            cpa16(d + 2*MATB,   Bh + off);
            cpa16(d + 3*MATB,   Bl + off);
        }
    };

    // prologue
#pragma unroll
    for (int s = 0; s < NS - 1; s++) {
        if (s < KS) load_stage(s, s);
        CPA_COMMIT();
    }

    // lane-invariant ldmatrix offsets
    const uint32_t a_row = (uint32_t)(wm * 64 + (lane & 15)) * PITCH;
    const uint32_t b_row = (uint32_t)(wn * 32 + (lane & 15)) * PITCH;
    const uint32_t lcol  = (uint32_t)((lane >> 4) * 16);

    for (int k = 0; k < KS; k++) {
        const int kl = k + NS - 1;
        if (kl < KS) load_stage(kl % NS, kl);
        CPA_COMMIT();
        CPA_WAIT2();                  // group k (= stage k) complete
        __syncthreads();

        const uint32_t st = sbase + (k % NS) * STG;
#pragma unroll
        for (int kc = 0; kc < 2; kc++) {
            const uint32_t col = kc * 32 + lcol;
            uint32_t ah[4][4], al[4][4], bh[2][4], bl[2][4];
#pragma unroll
            for (int mt = 0; mt < 4; mt++) {
                const uint32_t ad = st + a_row + (uint32_t)(mt * 16 * PITCH) + col;
                LDSM4(ah[mt], ad);
                LDSM4(al[mt], ad + MATB);
            }
#pragma unroll
            for (int np = 0; np < 2; np++) {
                const uint32_t bd = st + 2*MATB + b_row + (uint32_t)(np * 16 * PITCH) + col;
                LDSM4(bh[np], bd);
                LDSM4(bl[np], bd + MATB);
            }
#pragma unroll
            for (int mt = 0; mt < 4; mt++)
#pragma unroll
                for (int nt = 0; nt < 4; nt++) {
                    const int np = nt >> 1, i = nt & 1;
                    MMA_BF16(acc[mt][nt], ah[mt], bh[np][i], bh[np][i + 2]);
                    MMA_BF16(acc[mt][nt], ah[mt], bl[np][i], bl[np][i + 2]);
                    MMA_BF16(acc[mt][nt], al[mt], bh[np][i], bh[np][i + 2]);
                }
        }
        __syncthreads();
    }

    // ---------------- epilogue ----------------
#pragma unroll
    for (int mt = 0; mt < 4; mt++)
#pragma unroll
        for (int nt = 0; nt < 4; nt++) {
            const int m0 = bm + wm * 64 + mt * 16 + (lane >> 2);
            const int n0 = bn + wn * 32 + nt * 8 + (lane & 3) * 2;
            float b0 = 0.f, b1 = 0.f;
            if (bias) { b0 = bias[n0]; b1 = bias[n0 + 1]; }
#pragma unroll
            for (int half = 0; half < 2; half++) {
                const int m = m0 + half * 8;
                const float v0 = acc[mt][nt][half * 2 + 0] + b0;
                const float v1 = acc[mt][nt][half * 2 + 1] + b1;
                if (!scatter) {
                    float* cp = Cf + (long)z * sC + (long)m * N + n0;
                    cp[0] = v0; cp[1] = v1;
                } else {
                    const int b = m >> 10, t = m & 1023;
                    const int h = n0 >> 6, dh0 = n0 & 63;
                    const long base = (((long)(b * Hn + h) * Tn + t) * DHn) + dh0;
                    if (Cf) { Cf[base] = v0; Cf[base + 1] = v1; }
                    if (Ch) {
                        __nv_bfloat16 hh0 = __float2bfloat16(v0);
                        __nv_bfloat16 hh1 = __float2bfloat16(v1);
                        Ch[base]     = hh0;
                        Ch[base + 1] = hh1;
                        Cl[base]     = __float2bfloat16(v0 - __bfloat162float(hh0));
                        Cl[base + 1] = __float2bfloat16(v1 - __bfloat162float(hh1));
                    }
                }
            }
        }
}

// ---------------- qpe table: QPE[b,h,i,p] = sum_d Q[b,h,i,d] * pe[h,p,d] ----------------
__global__ __launch_bounds__(256) void qpe_kernel(const float* __restrict__ PE,
                                                  const float* __restrict__ Q,
                                                  float* __restrict__ QPE)
{
    const int it = blockIdx.x, bh = blockIdx.y, h = bh & (Hn - 1);
    const float* Aq = Q + ((long)bh * Tn + it * 64) * DHn;
    const float* Bp = PE + (long)h * MAXP * DHn;

    __shared__ float Qs[64][65];
    __shared__ float Ps[64][65];

    const int tid = threadIdx.x;
    const int rowb = tid >> 4, c4 = (tid & 15) << 2;
#pragma unroll
    for (int r = 0; r < 4; r++) {
        int row = rowb + r * 16;
        float4 q4 = *(const float4*)(Aq + (long)row * DHn + c4);
        Qs[row][c4] = q4.x; Qs[row][c4 + 1] = q4.y;
        Qs[row][c4 + 2] = q4.z; Qs[row][c4 + 3] = q4.w;
        float4 p4 = *(const float4*)(Bp + (long)row * DHn + c4);
        Ps[row][c4] = p4.x; Ps[row][c4 + 1] = p4.y;
        Ps[row][c4 + 2] = p4.z; Ps[row][c4 + 3] = p4.w;
    }
    __syncthreads();

    const int tx = tid & 15, ty = tid >> 4;
    float acc[4][4];
#pragma unroll
    for (int i = 0; i < 4; i++)
#pragma unroll
        for (int j = 0; j < 4; j++) acc[i][j] = 0.f;

#pragma unroll 16
    for (int kk = 0; kk < 64; kk++) {
        float a0 = Qs[ty * 4 + 0][kk], a1 = Qs[ty * 4 + 1][kk];
        float a2 = Qs[ty * 4 + 2][kk], a3 = Qs[ty * 4 + 3][kk];
        float b0 = Ps[tx * 4 + 0][kk], b1 = Ps[tx * 4 + 1][kk];
        float b2 = Ps[tx * 4 + 2][kk], b3 = Ps[tx * 4 + 3][kk];
        acc[0][0] = fmaf(a0, b0, acc[0][0]); acc[0][1] = fmaf(a0, b1, acc[0][1]);
        acc[0][2] = fmaf(a0, b2, acc[0][2]); acc[0][3] = fmaf(a0, b3, acc[0][3]);
        acc[1][0] = fmaf(a1, b0, acc[1][0]); acc[1][1] = fmaf(a1, b1, acc[1][1]);
        acc[1][2] = fmaf(a1, b2, acc[1][2]); acc[1][3] = fmaf(a1, b3, acc[1][3]);
        acc[2][0] = fmaf(a2, b0, acc[2][0]); acc[2][1] = fmaf(a2, b1, acc[2][1]);
        acc[2][2] = fmaf(a2, b2, acc[2][2]); acc[2][3] = fmaf(a2, b3, acc[2][3]);
        acc[3][0] = fmaf(a3, b0, acc[3][0]); acc[3][1] = fmaf(a3, b1, acc[3][1]);
        acc[3][2] = fmaf(a3, b2, acc[3][2]); acc[3][3] = fmaf(a3, b3, acc[3][3]);
    }

    float* out = QPE + ((long)bh * Tn + it * 64) * MAXP;
#pragma unroll
    for (int ii = 0; ii < 4; ii++) {
        float4 o4 = make_float4(acc[ii][0], acc[ii][1], acc[ii][2], acc[ii][3]);
        *(float4*)(out + (long)(ty * 4 + ii) * MAXP + tx * 4) = o4;
    }
}

// ---------------- CoPE gates + suffix-cumsum + interp + softmax ----------------
__global__ __launch_bounds__(256) void cope_kernel(float* __restrict__ S,
                                                   const float* __restrict__ QPE)
{
    const int i = blockIdx.x, bh = blockIdx.y;
    float* row = S + ((long)bh * Tn + i) * Tn;
    const float* qpe = QPE + ((long)bh * Tn + i) * MAXP;

    __shared__ float qpes[64];
    __shared__ float wred[8];
    __shared__ float wred2[8];

    const int tid = threadIdx.x, lane = tid & 31, wid = tid >> 5;
    if (tid < 64) qpes[tid] = qpe[tid];

    const int j0 = tid << 2;
    float4 s4 = *(const float4*)(row + j0);
    float qk[4] = {s4.x, s4.y, s4.z, s4.w};

    float lpre[4];
    float run = 0.f;
#pragma unroll
    for (int q = 0; q < 4; q++) {
        float gg = 0.f;
        if (j0 + q <= i)
            gg = __fdividef(1.f, 1.f + __expf(-0.125f * qk[q]));
        run += gg;
        lpre[q] = run;
    }

    float v = run;
#pragma unroll
    for (int o = 1; o < 32; o <<= 1) {
        float t = __shfl_up_sync(0xffffffffu, v, o);
        if (lane >= o) v += t;
    }
    if (lane == 31) wred[wid] = v;
    __syncthreads();
    if (tid < 8) {
        float w = wred[tid];
#pragma unroll
        for (int o = 1; o < 8; o <<= 1) {
            float t = __shfl_up_sync(0x000000ffu, w, o);
            if (tid >= o) w += t;
        }
        wred[tid] = w;
    }
    __syncthreads();
    const float base  = (v - run) + (wid ? wred[wid - 1] : 0.f);
    const float total = wred[7];

    float sc[4];
    float mx = -INFINITY;
#pragma unroll
    for (int q = 0; q < 4; q++) {
        float s_ = -INFINITY;
        if (j0 + q <= i) {
            float pos = total - (base + lpre[q]);
            pos = fminf(fmaxf(pos, 0.f), 63.f);
            float pf = floorf(pos);
            int fi = (int)pf;
            float al = pos - pf;
            int ci = (fi < 63) ? fi + 1 : 63;
            float qf = qpes[fi], qc = qpes[ci];
            float qv = qf + al * (qc - qf);
            s_ = 0.125f * (qk[q] + qv);
        }
        sc[q] = s_;
        mx = fmaxf(mx, s_);
    }
#pragma unroll
    for (int o = 16; o; o >>= 1) mx = fmaxf(mx, __shfl_xor_sync(0xffffffffu, mx, o));
    if (lane == 0) wred2[wid] = mx;
    __syncthreads();
    float bmax = wred2[0];
#pragma unroll
    for (int k = 1; k < 8; k++) bmax = fmaxf(bmax, wred2[k]);

    float p[4];
    float ssum = 0.f;
#pragma unroll
    for (int q = 0; q < 4; q++) {
        float e = (j0 + q <= i) ? __expf(sc[q] - bmax) : 0.f;
        p[q] = e;
        ssum += e;
    }
#pragma unroll
    for (int o = 16; o; o >>= 1) ssum += __shfl_xor_sync(0xffffffffu, ssum, o);
    __syncthreads();
    if (lane == 0) wred2[wid] = ssum;
    __syncthreads();
    float tot = 0.f;
#pragma unroll
    for (int k = 0; k < 8; k++) tot += wred2[k];
    const float inv = __fdividef(1.f, tot);

    float4 o4 = make_float4(p[0] * inv, p[1] * inv, p[2] * inv, p[3] * inv);
    *(float4*)(row + j0) = o4;
}

// ---------------- AO[b,t,(h,dh)] = sum_j P[i,j] * V[b,h,j,dh] ----------------
__global__ __launch_bounds__(256) void pv_kernel(const float* __restrict__ S,
                                                 const float* __restrict__ V,
                                                 float* __restrict__ AO)
{
    const int it = blockIdx.x, bh = blockIdx.y;
    const int b = bh >> 4, h = bh & 15;
    const float* Pr = S + ((long)bh * Tn + it * 64) * Tn;
    const float* Vr = V + (long)bh * Tn * DHn;

    __shared__ float Ps[64][65];
    __shared__ float Vs[64][68];

    const int tid = threadIdx.x;
    const int tx = tid & 15, ty = tid >> 4;
    const int rowb = tid >> 4, c4 = (tid & 15) << 2;

    float acc[4][4];
#pragma unroll
    for (int i = 0; i < 4; i++)
#pragma unroll
        for (int j = 0; j < 4; j++) acc[i][j] = 0.f;

    const int kend = it * 64 + 64;
    for (int k0 = 0; k0 < kend; k0 += 64) {
        __syncthreads();
#pragma unroll
        for (int r = 0; r < 4; r++) {
            int row = rowb + r * 16;
            float4 p4 = *(const float4*)(Pr + (long)row * Tn + k0 + c4);
            Ps[row][c4] = p4.x; Ps[row][c4 + 1] = p4.y;
            Ps[row][c4 + 2] = p4.z; Ps[row][c4 + 3] = p4.w;
            float4 v4 = *(const float4*)(Vr + (long)(k0 + row) * DHn + c4);
            *(float4*)&Vs[row][c4] = v4;
        }
        __syncthreads();
#pragma unroll 8
        for (int kk = 0; kk < 64; kk++) {
            float4 bv = *(const float4*)&Vs[kk][tx * 4];
#pragma unroll
            for (int ii = 0; ii < 4; ii++) {
                float a = Ps[ty * 4 + ii][kk];
                acc[ii][0] = fmaf(a, bv.x, acc[ii][0]);
                acc[ii][1] = fmaf(a, bv.y, acc[ii][1]);
                acc[ii][2] = fmaf(a, bv.z, acc[ii][2]);
                acc[ii][3] = fmaf(a, bv.w, acc[ii][3]);
            }
        }
    }

    float* out = AO + ((long)b * Tn + it * 64) * Dm + h * DHn;
#pragma unroll
    for (int ii = 0; ii < 4; ii++) {
        float4 o4 = make_float4(acc[ii][0], acc[ii][1], acc[ii][2], acc[ii][3]);
        *(float4*)(out + (long)(ty * 4 + ii) * Dm + tx * 4) = o4;
    }
}

// ---------------- launcher ----------------
extern "C" void kernel_launch(void* const* d_in, const int* in_sizes, int n_in,
                              void* d_out, int out_size)
{
    (void)in_sizes; (void)n_in; (void)out_size;
    const float* x  = (const float*)d_in[0];
    const float* Wq = (const float*)d_in[1];
    const float* bq = (const float*)d_in[2];
    const float* Wk = (const float*)d_in[3];
    const float* bk = (const float*)d_in[4];
    const float* Wv = (const float*)d_in[5];
    const float* bv = (const float*)d_in[6];
    const float* Wo = (const float*)d_in[7];
    const float* bo = (const float*)d_in[8];
    const float* pe = (const float*)d_in[9];
    float* out = (float*)d_out;

    float *Qf, *Vf, *QPEd, *Sd, *AOd;
    __nv_bfloat16 *xh, *xl, *Wqh, *Wql, *Wkh, *Wkl, *Wvh, *Wvl, *Woh, *Wol;
    __nv_bfloat16 *Qh, *Ql, *Kh, *Kl, *AOh, *AOl;
    cudaGetSymbolAddress((void**)&Qf, g_Qf);
    cudaGetSymbolAddress((void**)&Vf, g_Vf);
    cudaGetSymbolAddress((void**)&QPEd, g_QPE);
    cudaGetSymbolAddress((void**)&Sd, g_S);
    cudaGetSymbolAddress((void**)&AOd, g_AO);
    cudaGetSymbolAddress((void**)&xh, g_xh);   cudaGetSymbolAddress((void**)&xl, g_xl);
    cudaGetSymbolAddress((void**)&Wqh, g_Wqh); cudaGetSymbolAddress((void**)&Wql, g_Wql);
    cudaGetSymbolAddress((void**)&Wkh, g_Wkh); cudaGetSymbolAddress((void**)&Wkl, g_Wkl);
    cudaGetSymbolAddress((void**)&Wvh, g_Wvh); cudaGetSymbolAddress((void**)&Wvl, g_Wvl);
    cudaGetSymbolAddress((void**)&Woh, g_Woh); cudaGetSymbolAddress((void**)&Wol, g_Wol);
    cudaGetSymbolAddress((void**)&Qh, g_Qh);   cudaGetSymbolAddress((void**)&Ql, g_Ql);
    cudaGetSymbolAddress((void**)&Kh, g_Kh);   cudaGetSymbolAddress((void**)&Kl, g_Kl);
    cudaGetSymbolAddress((void**)&AOh, g_AOh); cudaGetSymbolAddress((void**)&AOl, g_AOl);

    static int smem_set = 0;
    if (!smem_set) {
        cudaFuncSetAttribute(mm_hmma, cudaFuncAttributeMaxDynamicSharedMemorySize, MM_SMEM);
        smem_set = 1;
    }

    dim3 blk(256);

    // split inputs to bf16 hi/lo
    splitk<<<2048, blk>>>(x, xh, xl, Bsz * Tn * Dm);
    splitk<<<1024, blk>>>(Wq, Wqh, Wql, Dm * Dm);
    splitk<<<1024, blk>>>(Wk, Wkh, Wkl, Dm * Dm);
    splitk<<<1024, blk>>>(Wv, Wvh, Wvl, Dm * Dm);
    splitk<<<1024, blk>>>(Wo, Woh, Wol, Dm * Dm);

    // projections (scatter to (b,h,t,dh))
    mm_hmma<<<dim3(8, 16, 1), blk, MM_SMEM>>>(xh, xl, Wqh, Wql, bq,
                                              Qf, Qh, Ql, 2048, 1024, 1024, 0, 0, 0, 1, 0);
    mm_hmma<<<dim3(8, 16, 1), blk, MM_SMEM>>>(xh, xl, Wkh, Wkl, bk,
                                              nullptr, Kh, Kl, 2048, 1024, 1024, 0, 0, 0, 1, 0);
    mm_hmma<<<dim3(8, 16, 1), blk, MM_SMEM>>>(xh, xl, Wvh, Wvl, bv,
                                              Vf, nullptr, nullptr, 2048, 1024, 1024, 0, 0, 0, 1, 0);

    // qk = Q @ K^T per (b,h), causal tile skip
    mm_hmma<<<dim3(8, 8, 32), blk, MM_SMEM>>>(Qh, Ql, Kh, Kl, nullptr,
                                              Sd, nullptr, nullptr, 1024, 1024, 64,
                                              (long)Tn * DHn, (long)Tn * DHn, (long)Tn * Tn, 0, 1);

    // qpe table
    qpe_kernel<<<dim3(16, 32), blk>>>(pe, Qf, QPEd);

    // gates + suffix cumsum + interp + softmax (in place on S)
    cope_kernel<<<dim3(1024, 32), blk>>>(Sd, QPEd);

    // attn @ V
    pv_kernel<<<dim3(16, 32), blk>>>(Sd, Vf, AOd);

    // output projection
    splitk<<<2048, blk>>>(AOd, AOh, AOl, Bsz * Tn * Dm);
    mm_hmma<<<dim3(8, 16, 1), blk, MM_SMEM>>>(AOh, AOl, Woh, Wol, bo,
                                              out, nullptr, nullptr, 2048, 1024, 1024, 0, 0, 0, 0, 0);
}

// round 4
// speedup vs baseline: 2.1555x; 1.1228x over previous
#include <cuda_runtime.h>
#include <cuda_bf16.h>
#include <math.h>
#include <stdint.h>

#define Bsz 2
#define Tn  1024
#define Dm  1024
#define Hn  16
#define DHn 64
#define BHn (Bsz*Hn)
#define MAXP 64

// ---------------- scratch (static device arrays; no allocation) ----------------
__device__ float g_Qf[BHn*Tn*DHn];           // fp32 Q (for qpe)
__device__ float g_Vf[BHn*Tn*DHn];           // fp32 V (for vtrans)
__device__ float g_QPE[BHn*Tn*MAXP];
__device__ float g_S[(long)BHn*Tn*Tn];       // qk scores fp32, 128MB
__device__ __nv_bfloat16 g_Ph[(long)BHn*Tn*Tn], g_Pl[(long)BHn*Tn*Tn];  // probs hi/lo
__device__ __nv_bfloat16 g_Vth[BHn*DHn*Tn], g_Vtl[BHn*DHn*Tn];          // V^T hi/lo
__device__ __nv_bfloat16 g_xh[Bsz*Tn*Dm],  g_xl[Bsz*Tn*Dm];
__device__ __nv_bfloat16 g_Wqh[Dm*Dm], g_Wql[Dm*Dm];
__device__ __nv_bfloat16 g_Wkh[Dm*Dm], g_Wkl[Dm*Dm];
__device__ __nv_bfloat16 g_Wvh[Dm*Dm], g_Wvl[Dm*Dm];
__device__ __nv_bfloat16 g_Woh[Dm*Dm], g_Wol[Dm*Dm];
__device__ __nv_bfloat16 g_Qh[BHn*Tn*DHn], g_Ql[BHn*Tn*DHn];
__device__ __nv_bfloat16 g_Kh[BHn*Tn*DHn], g_Kl[BHn*Tn*DHn];
__device__ __nv_bfloat16 g_AOh[Bsz*Tn*Dm], g_AOl[Bsz*Tn*Dm];

// ---------------- helpers ----------------
__device__ __forceinline__ uint32_t smem_u32(const void* p) {
    uint32_t a;
    asm("{ .reg .u64 t; cvta.to.shared.u64 t, %1; cvt.u32.u64 %0, t; }" : "=r"(a) : "l"(p));
    return a;
}
__device__ __forceinline__ void cpa16(uint32_t dst, const void* src) {
    asm volatile("cp.async.cg.shared.global [%0], [%1], 16;" :: "r"(dst), "l"(src));
}
#define CPA_COMMIT() asm volatile("cp.async.commit_group;" ::: "memory")
#define CPA_WAIT2()  asm volatile("cp.async.wait_group 2;" ::: "memory")
#define CPA_WAIT1()  asm volatile("cp.async.wait_group 1;" ::: "memory")
#define CPA_WAIT0()  asm volatile("cp.async.wait_group 0;" ::: "memory")

#define LDSM4(r, a) \
    asm volatile("ldmatrix.sync.aligned.m8n8.x4.shared.b16 {%0,%1,%2,%3}, [%4];" \
        : "=r"((r)[0]), "=r"((r)[1]), "=r"((r)[2]), "=r"((r)[3]) : "r"(a))

#define MMA_BF16(c, a, b0v, b1v) \
    asm volatile("mma.sync.aligned.m16n8k16.row.col.f32.bf16.bf16.f32 " \
        "{%0,%1,%2,%3},{%4,%5,%6,%7},{%8,%9},{%0,%1,%2,%3};" \
        : "+f"((c)[0]), "+f"((c)[1]), "+f"((c)[2]), "+f"((c)[3]) \
        : "r"((a)[0]), "r"((a)[1]), "r"((a)[2]), "r"((a)[3]), "r"(b0v), "r"(b1v))

// ---------------- split fp32 -> bf16 hi/lo ----------------
__global__ __launch_bounds__(256) void splitk(const float* __restrict__ s,
                                              __nv_bfloat16* __restrict__ h,
                                              __nv_bfloat16* __restrict__ l, int n)
{
    int i = (blockIdx.x * 256 + threadIdx.x) * 4;
    if (i >= n) return;
    float4 v = *(const float4*)(s + i);
    __nv_bfloat16 h0 = __float2bfloat16(v.x), h1 = __float2bfloat16(v.y);
    __nv_bfloat16 h2 = __float2bfloat16(v.z), h3 = __float2bfloat16(v.w);
    __nv_bfloat16 l0 = __float2bfloat16(v.x - __bfloat162float(h0));
    __nv_bfloat16 l1 = __float2bfloat16(v.y - __bfloat162float(h1));
    __nv_bfloat16 l2 = __float2bfloat16(v.z - __bfloat162float(h2));
    __nv_bfloat16 l3 = __float2bfloat16(v.w - __bfloat162float(h3));
    __nv_bfloat162 H0; H0.x = h0; H0.y = h1;
    __nv_bfloat162 H1; H1.x = h2; H1.y = h3;
    __nv_bfloat162 L0; L0.x = l0; L0.y = l1;
    __nv_bfloat162 L1; L1.x = l2; L1.y = l3;
    *(__nv_bfloat162*)(h + i)     = H0;
    *(__nv_bfloat162*)(h + i + 2) = H1;
    *(__nv_bfloat162*)(l + i)     = L0;
    *(__nv_bfloat162*)(l + i + 2) = L1;
}

// ---------------- HMMA split-bf16 GEMM: C = (Ahi+Alo)(Bhi+Blo)^T + bias --------
#define NS   3
#define PITCH 80
#define MATB (128*PITCH)
#define STG  (4*MATB)
#define MM_SMEM (NS*STG)

__global__ __launch_bounds__(256, 1) void mm_hmma(
    const __nv_bfloat16* __restrict__ Ahi, const __nv_bfloat16* __restrict__ Alo,
    const __nv_bfloat16* __restrict__ Bhi, const __nv_bfloat16* __restrict__ Blo,
    const float* __restrict__ bias,
    float* __restrict__ Cf, __nv_bfloat16* __restrict__ Ch, __nv_bfloat16* __restrict__ Cl,
    int M, int N, int K, long sA, long sB, long sC, int scatter, int causal)
{
    if (causal && blockIdx.x > blockIdx.y) return;

    extern __shared__ char dsm[];
    const uint32_t sbase = smem_u32(dsm);

    const int tid  = threadIdx.x;
    const int wid  = tid >> 5;
    const int lane = tid & 31;
    const int wm   = wid & 1;
    const int wn   = wid >> 1;
    const int z    = blockIdx.z;
    const int bm   = blockIdx.y * 128;
    const int bn   = blockIdx.x * 128;

    const __nv_bfloat16* Ah = Ahi + (long)z * sA + (long)bm * K;
    const __nv_bfloat16* Al = Alo + (long)z * sA + (long)bm * K;
    const __nv_bfloat16* Bh = Bhi + (long)z * sB + (long)bn * K;
    const __nv_bfloat16* Bl = Blo + (long)z * sB + (long)bn * K;

    float acc[4][4][4];
#pragma unroll
    for (int i = 0; i < 4; i++)
#pragma unroll
        for (int j = 0; j < 4; j++)
#pragma unroll
            for (int c = 0; c < 4; c++) acc[i][j][c] = 0.f;

    const int KS = K >> 5;

    auto load_stage = [&](int slot, int ks) {
        const uint32_t base = sbase + slot * STG;
        const int k0 = ks * 32;
#pragma unroll
        for (int c = tid; c < 512; c += 256) {
            const int r = c >> 2, seg = c & 3;
            const uint32_t d = base + r * PITCH + seg * 16;
            const long off = (long)r * K + k0 + seg * 8;
            cpa16(d,            Ah + off);
            cpa16(d + MATB,     Al + off);
            cpa16(d + 2*MATB,   Bh + off);
            cpa16(d + 3*MATB,   Bl + off);
        }
    };

#pragma unroll
    for (int s = 0; s < NS - 1; s++) {
        if (s < KS) load_stage(s, s);
        CPA_COMMIT();
    }

    const uint32_t a_row = (uint32_t)(wm * 64 + (lane & 15)) * PITCH;
    const uint32_t b_row = (uint32_t)(wn * 32 + (lane & 15)) * PITCH;
    const uint32_t lcol  = (uint32_t)((lane >> 4) * 16);

    for (int k = 0; k < KS; k++) {
        const int kl = k + NS - 1;
        if (kl < KS) load_stage(kl % NS, kl);
        CPA_COMMIT();
        CPA_WAIT2();
        __syncthreads();

        const uint32_t st = sbase + (k % NS) * STG;
#pragma unroll
        for (int kc = 0; kc < 2; kc++) {
            const uint32_t col = kc * 32 + lcol;
            uint32_t ah[4][4], al[4][4], bh[2][4], bl[2][4];
#pragma unroll
            for (int mt = 0; mt < 4; mt++) {
                const uint32_t ad = st + a_row + (uint32_t)(mt * 16 * PITCH) + col;
                LDSM4(ah[mt], ad);
                LDSM4(al[mt], ad + MATB);
            }
#pragma unroll
            for (int np = 0; np < 2; np++) {
                const uint32_t bd = st + 2*MATB + b_row + (uint32_t)(np * 16 * PITCH) + col;
                LDSM4(bh[np], bd);
                LDSM4(bl[np], bd + MATB);
            }
#pragma unroll
            for (int mt = 0; mt < 4; mt++)
#pragma unroll
                for (int nt = 0; nt < 4; nt++) {
                    const int np = nt >> 1, i = nt & 1;
                    MMA_BF16(acc[mt][nt], ah[mt], bh[np][i], bh[np][i + 2]);
                    MMA_BF16(acc[mt][nt], ah[mt], bl[np][i], bl[np][i + 2]);
                    MMA_BF16(acc[mt][nt], al[mt], bh[np][i], bh[np][i + 2]);
                }
        }
        __syncthreads();
    }

#pragma unroll
    for (int mt = 0; mt < 4; mt++)
#pragma unroll
        for (int nt = 0; nt < 4; nt++) {
            const int m0 = bm + wm * 64 + mt * 16 + (lane >> 2);
            const int n0 = bn + wn * 32 + nt * 8 + (lane & 3) * 2;
            float b0 = 0.f, b1 = 0.f;
            if (bias) { b0 = bias[n0]; b1 = bias[n0 + 1]; }
#pragma unroll
            for (int half = 0; half < 2; half++) {
                const int m = m0 + half * 8;
                const float v0 = acc[mt][nt][half * 2 + 0] + b0;
                const float v1 = acc[mt][nt][half * 2 + 1] + b1;
                if (!scatter) {
                    float* cp = Cf + (long)z * sC + (long)m * N + n0;
                    cp[0] = v0; cp[1] = v1;
                } else {
                    const int b = m >> 10, t = m & 1023;
                    const int h = n0 >> 6, dh0 = n0 & 63;
                    const long base = (((long)(b * Hn + h) * Tn + t) * DHn) + dh0;
                    if (Cf) { Cf[base] = v0; Cf[base + 1] = v1; }
                    if (Ch) {
                        __nv_bfloat16 hh0 = __float2bfloat16(v0);
                        __nv_bfloat16 hh1 = __float2bfloat16(v1);
                        Ch[base]     = hh0;
                        Ch[base + 1] = hh1;
                        Cl[base]     = __float2bfloat16(v0 - __bfloat162float(hh0));
                        Cl[base + 1] = __float2bfloat16(v1 - __bfloat162float(hh1));
                    }
                }
            }
        }
}

// ---------------- transpose V: (b,h,t,dh) fp32 -> (b,h,dh,t) bf16 hi/lo ----------------
__global__ __launch_bounds__(256) void vtrans(const float* __restrict__ V,
                                              __nv_bfloat16* __restrict__ Th,
                                              __nv_bfloat16* __restrict__ Tl)
{
    __shared__ float tile[32][33];
    const int bh = blockIdx.z;
    const int dh0 = blockIdx.y * 32;
    const int t0 = blockIdx.x * 32;
    const int tx = threadIdx.x & 31, ty = threadIdx.x >> 5;

    const float* src = V + ((long)bh * Tn + t0) * DHn + dh0;
#pragma unroll
    for (int k = 0; k < 4; k++) {
        int r = ty * 4 + k;
        tile[r][tx] = src[(long)r * DHn + tx];
    }
    __syncthreads();
    __nv_bfloat16* dh_ = Th + ((long)bh * DHn + dh0) * Tn + t0;
    __nv_bfloat16* dl_ = Tl + ((long)bh * DHn + dh0) * Tn + t0;
#pragma unroll
    for (int k = 0; k < 4; k++) {
        int a = ty * 4 + k;
        float v = tile[tx][a];
        __nv_bfloat16 hh = __float2bfloat16(v);
        dh_[(long)a * Tn + tx] = hh;
        dl_[(long)a * Tn + tx] = __float2bfloat16(v - __bfloat162float(hh));
    }
}

// ---------------- qpe table: QPE[b,h,i,p] = sum_d Q[b,h,i,d] * pe[h,p,d] ----------------
__global__ __launch_bounds__(256) void qpe_kernel(const float* __restrict__ PE,
                                                  const float* __restrict__ Q,
                                                  float* __restrict__ QPE)
{
    const int it = blockIdx.x, bh = blockIdx.y, h = bh & (Hn - 1);
    const float* Aq = Q + ((long)bh * Tn + it * 64) * DHn;
    const float* Bp = PE + (long)h * MAXP * DHn;

    __shared__ float Qs[64][65];
    __shared__ float Ps[64][65];

    const int tid = threadIdx.x;
    const int rowb = tid >> 4, c4 = (tid & 15) << 2;
#pragma unroll
    for (int r = 0; r < 4; r++) {
        int row = rowb + r * 16;
        float4 q4 = *(const float4*)(Aq + (long)row * DHn + c4);
        Qs[row][c4] = q4.x; Qs[row][c4 + 1] = q4.y;
        Qs[row][c4 + 2] = q4.z; Qs[row][c4 + 3] = q4.w;
        float4 p4 = *(const float4*)(Bp + (long)row * DHn + c4);
        Ps[row][c4] = p4.x; Ps[row][c4 + 1] = p4.y;
        Ps[row][c4 + 2] = p4.z; Ps[row][c4 + 3] = p4.w;
    }
    __syncthreads();

    const int tx = tid & 15, ty = tid >> 4;
    float acc[4][4];
#pragma unroll
    for (int i = 0; i < 4; i++)
#pragma unroll
        for (int j = 0; j < 4; j++) acc[i][j] = 0.f;

#pragma unroll 16
    for (int kk = 0; kk < 64; kk++) {
        float a0 = Qs[ty * 4 + 0][kk], a1 = Qs[ty * 4 + 1][kk];
        float a2 = Qs[ty * 4 + 2][kk], a3 = Qs[ty * 4 + 3][kk];
        float b0 = Ps[tx * 4 + 0][kk], b1 = Ps[tx * 4 + 1][kk];
        float b2 = Ps[tx * 4 + 2][kk], b3 = Ps[tx * 4 + 3][kk];
        acc[0][0] = fmaf(a0, b0, acc[0][0]); acc[0][1] = fmaf(a0, b1, acc[0][1]);
        acc[0][2] = fmaf(a0, b2, acc[0][2]); acc[0][3] = fmaf(a0, b3, acc[0][3]);
        acc[1][0] = fmaf(a1, b0, acc[1][0]); acc[1][1] = fmaf(a1, b1, acc[1][1]);
        acc[1][2] = fmaf(a1, b2, acc[1][2]); acc[1][3] = fmaf(a1, b3, acc[1][3]);
        acc[2][0] = fmaf(a2, b0, acc[2][0]); acc[2][1] = fmaf(a2, b1, acc[2][1]);
        acc[2][2] = fmaf(a2, b2, acc[2][2]); acc[2][3] = fmaf(a2, b3, acc[2][3]);
        acc[3][0] = fmaf(a3, b0, acc[3][0]); acc[3][1] = fmaf(a3, b1, acc[3][1]);
        acc[3][2] = fmaf(a3, b2, acc[3][2]); acc[3][3] = fmaf(a3, b3, acc[3][3]);
    }

    float* out = QPE + ((long)bh * Tn + it * 64) * MAXP;
#pragma unroll
    for (int ii = 0; ii < 4; ii++) {
        float4 o4 = make_float4(acc[ii][0], acc[ii][1], acc[ii][2], acc[ii][3]);
        *(float4*)(out + (long)(ty * 4 + ii) * MAXP + tx * 4) = o4;
    }
}

// ---------------- CoPE: gates + suffix-cumsum + interp + softmax -> bf16 hi/lo probs ------
__global__ __launch_bounds__(256) void cope_kernel(const float* __restrict__ S,
                                                   const float* __restrict__ QPE,
                                                   __nv_bfloat16* __restrict__ Ph,
                                                   __nv_bfloat16* __restrict__ Pl)
{
    const int i = blockIdx.x, bh = blockIdx.y;
    const float* row = S + ((long)bh * Tn + i) * Tn;
    const long prow = ((long)bh * Tn + i) * Tn;
    const float* qpe = QPE + ((long)bh * Tn + i) * MAXP;
    const int blockend = ((i >> 7) + 1) << 7;

    __shared__ float qpes[64];
    __shared__ float wred[8];
    __shared__ float wred2[8];

    const int tid = threadIdx.x, lane = tid & 31, wid = tid >> 5;
    if (tid < 64) qpes[tid] = qpe[tid];

    const int j0 = tid << 2;
    float qk[4] = {0.f, 0.f, 0.f, 0.f};
    if (j0 <= i) {
        float4 s4 = *(const float4*)(row + j0);
        qk[0] = s4.x; qk[1] = s4.y; qk[2] = s4.z; qk[3] = s4.w;
    }

    float lpre[4];
    float run = 0.f;
#pragma unroll
    for (int q = 0; q < 4; q++) {
        float gg = 0.f;
        if (j0 + q <= i)
            gg = __fdividef(1.f, 1.f + __expf(-0.125f * qk[q]));
        run += gg;
        lpre[q] = run;
    }

    float v = run;
#pragma unroll
    for (int o = 1; o < 32; o <<= 1) {
        float t = __shfl_up_sync(0xffffffffu, v, o);
        if (lane >= o) v += t;
    }
    if (lane == 31) wred[wid] = v;
    __syncthreads();
    if (tid < 8) {
        float w = wred[tid];
#pragma unroll
        for (int o = 1; o < 8; o <<= 1) {
            float t = __shfl_up_sync(0x000000ffu, w, o);
            if (tid >= o) w += t;
        }
        wred[tid] = w;
    }
    __syncthreads();
    const float base  = (v - run) + (wid ? wred[wid - 1] : 0.f);
    const float total = wred[7];

    float sc[4];
    float mx = -INFINITY;
#pragma unroll
    for (int q = 0; q < 4; q++) {
        float s_ = -INFINITY;
        if (j0 + q <= i) {
            float pos = total - (base + lpre[q]);
            pos = fminf(fmaxf(pos, 0.f), 63.f);
            float pf = floorf(pos);
            int fi = (int)pf;
            float al = pos - pf;
            int ci = (fi < 63) ? fi + 1 : 63;
            float qf = qpes[fi], qc = qpes[ci];
            float qv = qf + al * (qc - qf);
            s_ = 0.125f * (qk[q] + qv);
        }
        sc[q] = s_;
        mx = fmaxf(mx, s_);
    }
#pragma unroll
    for (int o = 16; o; o >>= 1) mx = fmaxf(mx, __shfl_xor_sync(0xffffffffu, mx, o));
    if (lane == 0) wred2[wid] = mx;
    __syncthreads();
    float bmax = wred2[0];
#pragma unroll
    for (int k = 1; k < 8; k++) bmax = fmaxf(bmax, wred2[k]);

    float p[4];
    float ssum = 0.f;
#pragma unroll
    for (int q = 0; q < 4; q++) {
        float e = (j0 + q <= i) ? __expf(sc[q] - bmax) : 0.f;
        p[q] = e;
        ssum += e;
    }
#pragma unroll
    for (int o = 16; o; o >>= 1) ssum += __shfl_xor_sync(0xffffffffu, ssum, o);
    __syncthreads();
    if (lane == 0) wred2[wid] = ssum;
    __syncthreads();
    float tot = 0.f;
#pragma unroll
    for (int k = 0; k < 8; k++) tot += wred2[k];
    const float inv = __fdividef(1.f, tot);

    if (j0 < blockend) {
        float v0 = p[0] * inv, v1 = p[1] * inv, v2 = p[2] * inv, v3 = p[3] * inv;
        __nv_bfloat16 h0 = __float2bfloat16(v0), h1 = __float2bfloat16(v1);
        __nv_bfloat16 h2 = __float2bfloat16(v2), h3 = __float2bfloat16(v3);
        __nv_bfloat162 H0; H0.x = h0; H0.y = h1;
        __nv_bfloat162 H1; H1.x = h2; H1.y = h3;
        __nv_bfloat162 L0, L1;
        L0.x = __float2bfloat16(v0 - __bfloat162float(h0));
        L0.y = __float2bfloat16(v1 - __bfloat162float(h1));
        L1.x = __float2bfloat16(v2 - __bfloat162float(h2));
        L1.y = __float2bfloat16(v3 - __bfloat162float(h3));
        *(__nv_bfloat162*)(Ph + prow + j0)     = H0;
        *(__nv_bfloat162*)(Ph + prow + j0 + 2) = H1;
        *(__nv_bfloat162*)(Pl + prow + j0)     = L0;
        *(__nv_bfloat162*)(Pl + prow + j0 + 2) = L1;
    }
}

// ---------------- pv HMMA: AO = P @ V, P [bh,1024,1024] hi/lo, Vt [bh,64,1024] hi/lo ----
// BM=128, BN=64, BK=64, 2-stage cp.async. Writes AOh/AOl (b,t,d) bf16.
#define PPITCH 144                  // 64 bf16 = 128B + 16 pad
#define PMATB (128*PPITCH)          // 18432
#define VMATB (64*PPITCH)           // 9216
#define PVSTG (2*PMATB + 2*VMATB)   // 55296
#define PV_SMEM (2*PVSTG)           // 110592

__global__ __launch_bounds__(256, 1) void pv_hmma(
    const __nv_bfloat16* __restrict__ Ph, const __nv_bfloat16* __restrict__ Pl,
    const __nv_bfloat16* __restrict__ Vth, const __nv_bfloat16* __restrict__ Vtl,
    __nv_bfloat16* __restrict__ AOh, __nv_bfloat16* __restrict__ AOl)
{
    extern __shared__ char dsm[];
    const uint32_t sbase = smem_u32(dsm);

    const int tid  = threadIdx.x;
    const int wid  = tid >> 5;
    const int lane = tid & 31;
    const int wm   = wid & 1;      // 2 m-halves of 64
    const int wn   = wid >> 1;     // 4 n-quarters of 16
    const int it   = blockIdx.x;   // 128-row tile
    const int bh   = blockIdx.y;
    const int b    = bh >> 4, h = bh & 15;

    const __nv_bfloat16* Pr_h = Ph + ((long)bh * Tn + it * 128) * Tn;
    const __nv_bfloat16* Pr_l = Pl + ((long)bh * Tn + it * 128) * Tn;
    const __nv_bfloat16* Vh_  = Vth + (long)bh * DHn * Tn;
    const __nv_bfloat16* Vl_  = Vtl + (long)bh * DHn * Tn;

    float acc[4][2][4];
#pragma unroll
    for (int i = 0; i < 4; i++)
#pragma unroll
        for (int j = 0; j < 2; j++)
#pragma unroll
            for (int c = 0; c < 4; c++) acc[i][j][c] = 0.f;

    const int KS = 2 * (it + 1);     // k-steps of 64, causal

    auto load_stage = [&](int slot, int ks) {
        const uint32_t base = sbase + slot * PVSTG;
        const int k0 = ks * 64;
#pragma unroll
        for (int c = tid; c < 1024; c += 256) {
            const int r = c >> 3, seg = c & 7;
            const uint32_t d = base + r * PPITCH + seg * 16;
            const long off = (long)r * Tn + k0 + seg * 8;
            cpa16(d,         Pr_h + off);
            cpa16(d + PMATB, Pr_l + off);
        }
#pragma unroll
        for (int c = tid; c < 512; c += 256) {
            const int r = c >> 3, seg = c & 7;
            const uint32_t d = base + 2*PMATB + r * PPITCH + seg * 16;
            const long off = (long)r * Tn + k0 + seg * 8;
            cpa16(d,         Vh_ + off);
            cpa16(d + VMATB, Vl_ + off);
        }
        CPA_COMMIT();
    };

    load_stage(0, 0);

    const uint32_t a_row = (uint32_t)(wm * 64 + (lane & 15)) * PPITCH;
    const uint32_t b_row = (uint32_t)(wn * 16 + (lane & 15)) * PPITCH;
    const uint32_t lcol  = (uint32_t)((lane >> 4) * 16);

    for (int k = 0; k < KS; k++) {
        if (k + 1 < KS) load_stage((k + 1) & 1, k + 1);
        if (k + 1 < KS) { CPA_WAIT1(); } else { CPA_WAIT0(); }
        __syncthreads();

        const uint32_t st = sbase + (k & 1) * PVSTG;
#pragma unroll
        for (int kc = 0; kc < 4; kc++) {
            const uint32_t col = kc * 32 + lcol;
            uint32_t ah[4][4], al[4][4], bh4[4], bl4[4];
#pragma unroll
            for (int mt = 0; mt < 4; mt++) {
                const uint32_t ad = st + a_row + (uint32_t)(mt * 16 * PPITCH) + col;
                LDSM4(ah[mt], ad);
                LDSM4(al[mt], ad + PMATB);
            }
            {
                const uint32_t bd = st + 2*PMATB + b_row + col;
                LDSM4(bh4, bd);
                LDSM4(bl4, bd + VMATB);
            }
#pragma unroll
            for (int mt = 0; mt < 4; mt++)
#pragma unroll
                for (int nt = 0; nt < 2; nt++) {
                    MMA_BF16(acc[mt][nt], ah[mt], bh4[nt], bh4[nt + 2]);
                    MMA_BF16(acc[mt][nt], ah[mt], bl4[nt], bl4[nt + 2]);
                    MMA_BF16(acc[mt][nt], al[mt], bh4[nt], bh4[nt + 2]);
                }
        }
        __syncthreads();
    }

    // epilogue: write AOh/AOl at (b, t=i, h*64+dh)
#pragma unroll
    for (int mt = 0; mt < 4; mt++)
#pragma unroll
        for (int nt = 0; nt < 2; nt++) {
            const int i0 = it * 128 + wm * 64 + mt * 16 + (lane >> 2);
            const int dh = wn * 16 + nt * 8 + (lane & 3) * 2;
#pragma unroll
            for (int half = 0; half < 2; half++) {
                const int t = i0 + half * 8;
                const float v0 = acc[mt][nt][half * 2 + 0];
                const float v1 = acc[mt][nt][half * 2 + 1];
                const long base = ((long)b * Tn + t) * Dm + h * 64 + dh;
                __nv_bfloat16 h0 = __float2bfloat16(v0);
                __nv_bfloat16 h1 = __float2bfloat16(v1);
                __nv_bfloat162 H; H.x = h0; H.y = h1;
                __nv_bfloat162 L;
                L.x = __float2bfloat16(v0 - __bfloat162float(h0));
                L.y = __float2bfloat16(v1 - __bfloat162float(h1));
                *(__nv_bfloat162*)(AOh + base) = H;
                *(__nv_bfloat162*)(AOl + base) = L;
            }
        }
}

// ---------------- launcher ----------------
extern "C" void kernel_launch(void* const* d_in, const int* in_sizes, int n_in,
                              void* d_out, int out_size)
{
    (void)in_sizes; (void)n_in; (void)out_size;
    const float* x  = (const float*)d_in[0];
    const float* Wq = (const float*)d_in[1];
    const float* bq = (const float*)d_in[2];
    const float* Wk = (const float*)d_in[3];
    const float* bk = (const float*)d_in[4];
    const float* Wv = (const float*)d_in[5];
    const float* bv = (const float*)d_in[6];
    const float* Wo = (const float*)d_in[7];
    const float* bo = (const float*)d_in[8];
    const float* pe = (const float*)d_in[9];
    float* out = (float*)d_out;

    float *Qf, *Vf, *QPEd, *Sd;
    __nv_bfloat16 *xh, *xl, *Wqh, *Wql, *Wkh, *Wkl, *Wvh, *Wvl, *Woh, *Wol;
    __nv_bfloat16 *Qh, *Ql, *Kh, *Kl, *AOh, *AOl, *Phd, *Pld, *Vth, *Vtl;
    cudaGetSymbolAddress((void**)&Qf, g_Qf);
    cudaGetSymbolAddress((void**)&Vf, g_Vf);
    cudaGetSymbolAddress((void**)&QPEd, g_QPE);
    cudaGetSymbolAddress((void**)&Sd, g_S);
    cudaGetSymbolAddress((void**)&xh, g_xh);   cudaGetSymbolAddress((void**)&xl, g_xl);
    cudaGetSymbolAddress((void**)&Wqh, g_Wqh); cudaGetSymbolAddress((void**)&Wql, g_Wql);
    cudaGetSymbolAddress((void**)&Wkh, g_Wkh); cudaGetSymbolAddress((void**)&Wkl, g_Wkl);
    cudaGetSymbolAddress((void**)&Wvh, g_Wvh); cudaGetSymbolAddress((void**)&Wvl, g_Wvl);
    cudaGetSymbolAddress((void**)&Woh, g_Woh); cudaGetSymbolAddress((void**)&Wol, g_Wol);
    cudaGetSymbolAddress((void**)&Qh, g_Qh);   cudaGetSymbolAddress((void**)&Ql, g_Ql);
    cudaGetSymbolAddress((void**)&Kh, g_Kh);   cudaGetSymbolAddress((void**)&Kl, g_Kl);
    cudaGetSymbolAddress((void**)&AOh, g_AOh); cudaGetSymbolAddress((void**)&AOl, g_AOl);
    cudaGetSymbolAddress((void**)&Phd, g_Ph);  cudaGetSymbolAddress((void**)&Pld, g_Pl);
    cudaGetSymbolAddress((void**)&Vth, g_Vth); cudaGetSymbolAddress((void**)&Vtl, g_Vtl);

    static int smem_set = 0;
    if (!smem_set) {
        cudaFuncSetAttribute(mm_hmma, cudaFuncAttributeMaxDynamicSharedMemorySize, MM_SMEM);
        cudaFuncSetAttribute(pv_hmma, cudaFuncAttributeMaxDynamicSharedMemorySize, PV_SMEM);
        smem_set = 1;
    }

    dim3 blk(256);

    splitk<<<2048, blk>>>(x, xh, xl, Bsz * Tn * Dm);
    splitk<<<1024, blk>>>(Wq, Wqh, Wql, Dm * Dm);
    splitk<<<1024, blk>>>(Wk, Wkh, Wkl, Dm * Dm);
    splitk<<<1024, blk>>>(Wv, Wvh, Wvl, Dm * Dm);
    splitk<<<1024, blk>>>(Wo, Woh, Wol, Dm * Dm);

    mm_hmma<<<dim3(8, 16, 1), blk, MM_SMEM>>>(xh, xl, Wqh, Wql, bq,
                                              Qf, Qh, Ql, 2048, 1024, 1024, 0, 0, 0, 1, 0);
    mm_hmma<<<dim3(8, 16, 1), blk, MM_SMEM>>>(xh, xl, Wkh, Wkl, bk,
                                              nullptr, Kh, Kl, 2048, 1024, 1024, 0, 0, 0, 1, 0);
    mm_hmma<<<dim3(8, 16, 1), blk, MM_SMEM>>>(xh, xl, Wvh, Wvl, bv,
                                              Vf, nullptr, nullptr, 2048, 1024, 1024, 0, 0, 0, 1, 0);

    mm_hmma<<<dim3(8, 8, 32), blk, MM_SMEM>>>(Qh, Ql, Kh, Kl, nullptr,
                                              Sd, nullptr, nullptr, 1024, 1024, 64,
                                              (long)Tn * DHn, (long)Tn * DHn, (long)Tn * Tn, 0, 1);

    qpe_kernel<<<dim3(16, 32), blk>>>(pe, Qf, QPEd);
    vtrans<<<dim3(32, 2, 32), blk>>>(Vf, Vth, Vtl);

    cope_kernel<<<dim3(1024, 32), blk>>>(Sd, QPEd, Phd, Pld);

    pv_hmma<<<dim3(8, 32), blk, PV_SMEM>>>(Phd, Pld, Vth, Vtl, AOh, AOl);

    mm_hmma<<<dim3(8, 16, 1), blk, MM_SMEM>>>(AOh, AOl, Woh, Wol, bo,
                                              out, nullptr, nullptr, 2048, 1024, 1024, 0, 0, 0, 0, 0);
}

// round 5
// speedup vs baseline: 2.1905x; 1.0162x over previous
#include <cuda_runtime.h>
#include <cuda_bf16.h>
#include <math.h>
#include <stdint.h>

#define Bsz 2
#define Tn  1024
#define Dm  1024
#define Hn  16
#define DHn 64
#define BHn (Bsz*Hn)
#define MAXP 64

// ---------------- scratch (static device arrays; no allocation) ----------------
__device__ float g_Qf[BHn*Tn*DHn];           // fp32 Q (for qpe)
__device__ float g_QPE[BHn*Tn*MAXP];
__device__ float g_S[(long)BHn*Tn*Tn];       // qk scores fp32, 128MB
__device__ __nv_bfloat16 g_Ph[(long)BHn*Tn*Tn], g_Pl[(long)BHn*Tn*Tn];  // probs hi/lo
__device__ __nv_bfloat16 g_Vth[BHn*DHn*Tn], g_Vtl[BHn*DHn*Tn];          // V^T hi/lo
__device__ __nv_bfloat16 g_xh[Bsz*Tn*Dm],  g_xl[Bsz*Tn*Dm];
__device__ __nv_bfloat16 g_Wqh[Dm*Dm], g_Wql[Dm*Dm];
__device__ __nv_bfloat16 g_Wkh[Dm*Dm], g_Wkl[Dm*Dm];
__device__ __nv_bfloat16 g_Wvh[Dm*Dm], g_Wvl[Dm*Dm];
__device__ __nv_bfloat16 g_Woh[Dm*Dm], g_Wol[Dm*Dm];
__device__ __nv_bfloat16 g_Qh[BHn*Tn*DHn], g_Ql[BHn*Tn*DHn];
__device__ __nv_bfloat16 g_Kh[BHn*Tn*DHn], g_Kl[BHn*Tn*DHn];
__device__ __nv_bfloat16 g_AOh[Bsz*Tn*Dm], g_AOl[Bsz*Tn*Dm];

// ---------------- helpers ----------------
__device__ __forceinline__ uint32_t smem_u32(const void* p) {
    uint32_t a;
    asm("{ .reg .u64 t; cvta.to.shared.u64 t, %1; cvt.u32.u64 %0, t; }" : "=r"(a) : "l"(p));
    return a;
}
__device__ __forceinline__ void cpa16(uint32_t dst, const void* src) {
    asm volatile("cp.async.cg.shared.global [%0], [%1], 16;" :: "r"(dst), "l"(src));
}
#define CPA_COMMIT() asm volatile("cp.async.commit_group;" ::: "memory")
#define CPA_WAIT2()  asm volatile("cp.async.wait_group 2;" ::: "memory")
#define CPA_WAIT1()  asm volatile("cp.async.wait_group 1;" ::: "memory")
#define CPA_WAIT0()  asm volatile("cp.async.wait_group 0;" ::: "memory")

#define LDSM4(r, a) \
    asm volatile("ldmatrix.sync.aligned.m8n8.x4.shared.b16 {%0,%1,%2,%3}, [%4];" \
        : "=r"((r)[0]), "=r"((r)[1]), "=r"((r)[2]), "=r"((r)[3]) : "r"(a))

#define MMA_BF16(c, a, b0v, b1v) \
    asm volatile("mma.sync.aligned.m16n8k16.row.col.f32.bf16.bf16.f32 " \
        "{%0,%1,%2,%3},{%4,%5,%6,%7},{%8,%9},{%0,%1,%2,%3};" \
        : "+f"((c)[0]), "+f"((c)[1]), "+f"((c)[2]), "+f"((c)[3]) \
        : "r"((a)[0]), "r"((a)[1]), "r"((a)[2]), "r"((a)[3]), "r"(b0v), "r"(b1v))

// ---------------- split fp32 -> bf16 hi/lo ----------------
__global__ __launch_bounds__(256) void splitk(const float* __restrict__ s,
                                              __nv_bfloat16* __restrict__ h,
                                              __nv_bfloat16* __restrict__ l, int n)
{
    int i = (blockIdx.x * 256 + threadIdx.x) * 4;
    if (i >= n) return;
    float4 v = *(const float4*)(s + i);
    __nv_bfloat16 h0 = __float2bfloat16(v.x), h1 = __float2bfloat16(v.y);
    __nv_bfloat16 h2 = __float2bfloat16(v.z), h3 = __float2bfloat16(v.w);
    __nv_bfloat16 l0 = __float2bfloat16(v.x - __bfloat162float(h0));
    __nv_bfloat16 l1 = __float2bfloat16(v.y - __bfloat162float(h1));
    __nv_bfloat16 l2 = __float2bfloat16(v.z - __bfloat162float(h2));
    __nv_bfloat16 l3 = __float2bfloat16(v.w - __bfloat162float(h3));
    __nv_bfloat162 H0; H0.x = h0; H0.y = h1;
    __nv_bfloat162 H1; H1.x = h2; H1.y = h3;
    __nv_bfloat162 L0; L0.x = l0; L0.y = l1;
    __nv_bfloat162 L1; L1.x = l2; L1.y = l3;
    *(__nv_bfloat162*)(h + i)     = H0;
    *(__nv_bfloat162*)(h + i + 2) = H1;
    *(__nv_bfloat162*)(l + i)     = L0;
    *(__nv_bfloat162*)(l + i + 2) = L1;
}

// ---------------- common GEMM tile params ----------------
#define NS   3
#define PITCH 80
#define MATB (128*PITCH)
#define STG  (4*MATB)
#define MM_SMEM (NS*STG)

// ---------------- merged QKV projection GEMM, z = blockIdx.z selects Q/K/V ------
// A = x (2048 x 1024) hi/lo; B = W_z (1024 x 1024) hi/lo; C scattered per z:
//  z=0: Qf fp32 + Qh/Ql (b,h,t,dh);  z=1: Kh/Kl;  z=2: Vth/Vtl transposed (b,h,dh,t)
__global__ __launch_bounds__(256, 1) void qkv_hmma(
    const __nv_bfloat16* __restrict__ xh, const __nv_bfloat16* __restrict__ xl,
    const __nv_bfloat16* __restrict__ Wqh, const __nv_bfloat16* __restrict__ Wql,
    const __nv_bfloat16* __restrict__ Wkh, const __nv_bfloat16* __restrict__ Wkl,
    const __nv_bfloat16* __restrict__ Wvh, const __nv_bfloat16* __restrict__ Wvl,
    const float* __restrict__ bq, const float* __restrict__ bk, const float* __restrict__ bv,
    float* __restrict__ Qf,
    __nv_bfloat16* __restrict__ Qh, __nv_bfloat16* __restrict__ Ql,
    __nv_bfloat16* __restrict__ Kh, __nv_bfloat16* __restrict__ Kl,
    __nv_bfloat16* __restrict__ Vth, __nv_bfloat16* __restrict__ Vtl)
{
    extern __shared__ char dsm[];
    const uint32_t sbase = smem_u32(dsm);

    const int tid  = threadIdx.x;
    const int wid  = tid >> 5;
    const int lane = tid & 31;
    const int wm   = wid & 1;
    const int wn   = wid >> 1;
    const int z    = blockIdx.z;
    const int bm   = blockIdx.y * 128;
    const int bn   = blockIdx.x * 128;
    const int K    = 1024;

    const __nv_bfloat16* Bh_ = (z == 0) ? Wqh : (z == 1) ? Wkh : Wvh;
    const __nv_bfloat16* Bl_ = (z == 0) ? Wql : (z == 1) ? Wkl : Wvl;
    const float* bias = (z == 0) ? bq : (z == 1) ? bk : bv;

    const __nv_bfloat16* Ah = xh + (long)bm * K;
    const __nv_bfloat16* Al = xl + (long)bm * K;
    const __nv_bfloat16* Bh = Bh_ + (long)bn * K;
    const __nv_bfloat16* Bl = Bl_ + (long)bn * K;

    float acc[4][4][4];
#pragma unroll
    for (int i = 0; i < 4; i++)
#pragma unroll
        for (int j = 0; j < 4; j++)
#pragma unroll
            for (int c = 0; c < 4; c++) acc[i][j][c] = 0.f;

    const int KS = K >> 5;

    auto load_stage = [&](int slot, int ks) {
        const uint32_t base = sbase + slot * STG;
        const int k0 = ks * 32;
#pragma unroll
        for (int c = tid; c < 512; c += 256) {
            const int r = c >> 2, seg = c & 3;
            const uint32_t d = base + r * PITCH + seg * 16;
            const long off = (long)r * K + k0 + seg * 8;
            cpa16(d,            Ah + off);
            cpa16(d + MATB,     Al + off);
            cpa16(d + 2*MATB,   Bh + off);
            cpa16(d + 3*MATB,   Bl + off);
        }
    };

#pragma unroll
    for (int s = 0; s < NS - 1; s++) {
        load_stage(s, s);
        CPA_COMMIT();
    }

    const uint32_t a_row = (uint32_t)(wm * 64 + (lane & 15)) * PITCH;
    const uint32_t b_row = (uint32_t)(wn * 32 + (lane & 15)) * PITCH;
    const uint32_t lcol  = (uint32_t)((lane >> 4) * 16);

    for (int k = 0; k < KS; k++) {
        const int kl = k + NS - 1;
        if (kl < KS) load_stage(kl % NS, kl);
        CPA_COMMIT();
        CPA_WAIT2();
        __syncthreads();

        const uint32_t st = sbase + (k % NS) * STG;
#pragma unroll
        for (int kc = 0; kc < 2; kc++) {
            const uint32_t col = kc * 32 + lcol;
            uint32_t ah[4][4], al[4][4], bh[2][4], bl[2][4];
#pragma unroll
            for (int mt = 0; mt < 4; mt++) {
                const uint32_t ad = st + a_row + (uint32_t)(mt * 16 * PITCH) + col;
                LDSM4(ah[mt], ad);
                LDSM4(al[mt], ad + MATB);
            }
#pragma unroll
            for (int np = 0; np < 2; np++) {
                const uint32_t bd = st + 2*MATB + b_row + (uint32_t)(np * 16 * PITCH) + col;
                LDSM4(bh[np], bd);
                LDSM4(bl[np], bd + MATB);
            }
#pragma unroll
            for (int mt = 0; mt < 4; mt++)
#pragma unroll
                for (int nt = 0; nt < 4; nt++) {
                    const int np = nt >> 1, i = nt & 1;
                    MMA_BF16(acc[mt][nt], ah[mt], bh[np][i], bh[np][i + 2]);
                    MMA_BF16(acc[mt][nt], ah[mt], bl[np][i], bl[np][i + 2]);
                    MMA_BF16(acc[mt][nt], al[mt], bh[np][i], bh[np][i + 2]);
                }
        }
        __syncthreads();
    }

#pragma unroll
    for (int mt = 0; mt < 4; mt++)
#pragma unroll
        for (int nt = 0; nt < 4; nt++) {
            const int m0 = bm + wm * 64 + mt * 16 + (lane >> 2);
            const int n0 = bn + wn * 32 + nt * 8 + (lane & 3) * 2;
            const float b0 = bias[n0], b1 = bias[n0 + 1];
            const int h = n0 >> 6, dh0 = n0 & 63;
#pragma unroll
            for (int half = 0; half < 2; half++) {
                const int m = m0 + half * 8;
                const float v0 = acc[mt][nt][half * 2 + 0] + b0;
                const float v1 = acc[mt][nt][half * 2 + 1] + b1;
                const int b = m >> 10, t = m & 1023;
                __nv_bfloat16 hh0 = __float2bfloat16(v0);
                __nv_bfloat16 hh1 = __float2bfloat16(v1);
                __nv_bfloat16 ll0 = __float2bfloat16(v0 - __bfloat162float(hh0));
                __nv_bfloat16 ll1 = __float2bfloat16(v1 - __bfloat162float(hh1));
                if (z == 2) {
                    // transposed: Vt[(b,h), dh, t]
                    const long tb = (((long)(b * Hn + h) * DHn + dh0) * Tn) + t;
                    Vth[tb]      = hh0;  Vtl[tb]      = ll0;
                    Vth[tb + Tn] = hh1;  Vtl[tb + Tn] = ll1;
                } else {
                    const long base = (((long)(b * Hn + h) * Tn + t) * DHn) + dh0;
                    if (z == 0) {
                        Qf[base] = v0; Qf[base + 1] = v1;
                        Qh[base] = hh0; Qh[base + 1] = hh1;
                        Ql[base] = ll0; Ql[base + 1] = ll1;
                    } else {
                        Kh[base] = hh0; Kh[base + 1] = hh1;
                        Kl[base] = ll0; Kl[base + 1] = ll1;
                    }
                }
            }
        }
}

// ---------------- HMMA split-bf16 GEMM: C = (Ahi+Alo)(Bhi+Blo)^T + bias --------
__global__ __launch_bounds__(256, 1) void mm_hmma(
    const __nv_bfloat16* __restrict__ Ahi, const __nv_bfloat16* __restrict__ Alo,
    const __nv_bfloat16* __restrict__ Bhi, const __nv_bfloat16* __restrict__ Blo,
    const float* __restrict__ bias,
    float* __restrict__ Cf,
    int M, int N, int K, long sA, long sB, long sC, int causal)
{
    if (causal && blockIdx.x > blockIdx.y) return;

    extern __shared__ char dsm[];
    const uint32_t sbase = smem_u32(dsm);

    const int tid  = threadIdx.x;
    const int wid  = tid >> 5;
    const int lane = tid & 31;
    const int wm   = wid & 1;
    const int wn   = wid >> 1;
    const int z    = blockIdx.z;
    const int bm   = blockIdx.y * 128;
    const int bn   = blockIdx.x * 128;

    const __nv_bfloat16* Ah = Ahi + (long)z * sA + (long)bm * K;
    const __nv_bfloat16* Al = Alo + (long)z * sA + (long)bm * K;
    const __nv_bfloat16* Bh = Bhi + (long)z * sB + (long)bn * K;
    const __nv_bfloat16* Bl = Blo + (long)z * sB + (long)bn * K;

    float acc[4][4][4];
#pragma unroll
    for (int i = 0; i < 4; i++)
#pragma unroll
        for (int j = 0; j < 4; j++)
#pragma unroll
            for (int c = 0; c < 4; c++) acc[i][j][c] = 0.f;

    const int KS = K >> 5;

    auto load_stage = [&](int slot, int ks) {
        const uint32_t base = sbase + slot * STG;
        const int k0 = ks * 32;
#pragma unroll
        for (int c = tid; c < 512; c += 256) {
            const int r = c >> 2, seg = c & 3;
            const uint32_t d = base + r * PITCH + seg * 16;
            const long off = (long)r * K + k0 + seg * 8;
            cpa16(d,            Ah + off);
            cpa16(d + MATB,     Al + off);
            cpa16(d + 2*MATB,   Bh + off);
            cpa16(d + 3*MATB,   Bl + off);
        }
    };

#pragma unroll
    for (int s = 0; s < NS - 1; s++) {
        if (s < KS) load_stage(s, s);
        CPA_COMMIT();
    }

    const uint32_t a_row = (uint32_t)(wm * 64 + (lane & 15)) * PITCH;
    const uint32_t b_row = (uint32_t)(wn * 32 + (lane & 15)) * PITCH;
    const uint32_t lcol  = (uint32_t)((lane >> 4) * 16);

    for (int k = 0; k < KS; k++) {
        const int kl = k + NS - 1;
        if (kl < KS) load_stage(kl % NS, kl);
        CPA_COMMIT();
        CPA_WAIT2();
        __syncthreads();

        const uint32_t st = sbase + (k % NS) * STG;
#pragma unroll
        for (int kc = 0; kc < 2; kc++) {
            const uint32_t col = kc * 32 + lcol;
            uint32_t ah[4][4], al[4][4], bh[2][4], bl[2][4];
#pragma unroll
            for (int mt = 0; mt < 4; mt++) {
                const uint32_t ad = st + a_row + (uint32_t)(mt * 16 * PITCH) + col;
                LDSM4(ah[mt], ad);
                LDSM4(al[mt], ad + MATB);
            }
#pragma unroll
            for (int np = 0; np < 2; np++) {
                const uint32_t bd = st + 2*MATB + b_row + (uint32_t)(np * 16 * PITCH) + col;
                LDSM4(bh[np], bd);
                LDSM4(bl[np], bd + MATB);
            }
#pragma unroll
            for (int mt = 0; mt < 4; mt++)
#pragma unroll
                for (int nt = 0; nt < 4; nt++) {
                    const int np = nt >> 1, i = nt & 1;
                    MMA_BF16(acc[mt][nt], ah[mt], bh[np][i], bh[np][i + 2]);
                    MMA_BF16(acc[mt][nt], ah[mt], bl[np][i], bl[np][i + 2]);
                    MMA_BF16(acc[mt][nt], al[mt], bh[np][i], bh[np][i + 2]);
                }
        }
        __syncthreads();
    }

#pragma unroll
    for (int mt = 0; mt < 4; mt++)
#pragma unroll
        for (int nt = 0; nt < 4; nt++) {
            const int m0 = bm + wm * 64 + mt * 16 + (lane >> 2);
            const int n0 = bn + wn * 32 + nt * 8 + (lane & 3) * 2;
            float b0 = 0.f, b1 = 0.f;
            if (bias) { b0 = bias[n0]; b1 = bias[n0 + 1]; }
#pragma unroll
            for (int half = 0; half < 2; half++) {
                const int m = m0 + half * 8;
                float* cp = Cf + (long)z * sC + (long)m * N + n0;
                cp[0] = acc[mt][nt][half * 2 + 0] + b0;
                cp[1] = acc[mt][nt][half * 2 + 1] + b1;
            }
        }
}

// ---------------- qpe table: QPE[b,h,i,p] = sum_d Q[b,h,i,d] * pe[h,p,d] ----------------
__global__ __launch_bounds__(256) void qpe_kernel(const float* __restrict__ PE,
                                                  const float* __restrict__ Q,
                                                  float* __restrict__ QPE)
{
    const int it = blockIdx.x, bh = blockIdx.y, h = bh & (Hn - 1);
    const float* Aq = Q + ((long)bh * Tn + it * 64) * DHn;
    const float* Bp = PE + (long)h * MAXP * DHn;

    __shared__ float Qs[64][65];
    __shared__ float Ps[64][65];

    const int tid = threadIdx.x;
    const int rowb = tid >> 4, c4 = (tid & 15) << 2;
#pragma unroll
    for (int r = 0; r < 4; r++) {
        int row = rowb + r * 16;
        float4 q4 = *(const float4*)(Aq + (long)row * DHn + c4);
        Qs[row][c4] = q4.x; Qs[row][c4 + 1] = q4.y;
        Qs[row][c4 + 2] = q4.z; Qs[row][c4 + 3] = q4.w;
        float4 p4 = *(const float4*)(Bp + (long)row * DHn + c4);
        Ps[row][c4] = p4.x; Ps[row][c4 + 1] = p4.y;
        Ps[row][c4 + 2] = p4.z; Ps[row][c4 + 3] = p4.w;
    }
    __syncthreads();

    const int tx = tid & 15, ty = tid >> 4;
    float acc[4][4];
#pragma unroll
    for (int i = 0; i < 4; i++)
#pragma unroll
        for (int j = 0; j < 4; j++) acc[i][j] = 0.f;

#pragma unroll 16
    for (int kk = 0; kk < 64; kk++) {
        float a0 = Qs[ty * 4 + 0][kk], a1 = Qs[ty * 4 + 1][kk];
        float a2 = Qs[ty * 4 + 2][kk], a3 = Qs[ty * 4 + 3][kk];
        float b0 = Ps[tx * 4 + 0][kk], b1 = Ps[tx * 4 + 1][kk];
        float b2 = Ps[tx * 4 + 2][kk], b3 = Ps[tx * 4 + 3][kk];
        acc[0][0] = fmaf(a0, b0, acc[0][0]); acc[0][1] = fmaf(a0, b1, acc[0][1]);
        acc[0][2] = fmaf(a0, b2, acc[0][2]); acc[0][3] = fmaf(a0, b3, acc[0][3]);
        acc[1][0] = fmaf(a1, b0, acc[1][0]); acc[1][1] = fmaf(a1, b1, acc[1][1]);
        acc[1][2] = fmaf(a1, b2, acc[1][2]); acc[1][3] = fmaf(a1, b3, acc[1][3]);
        acc[2][0] = fmaf(a2, b0, acc[2][0]); acc[2][1] = fmaf(a2, b1, acc[2][1]);
        acc[2][2] = fmaf(a2, b2, acc[2][2]); acc[2][3] = fmaf(a2, b3, acc[2][3]);
        acc[3][0] = fmaf(a3, b0, acc[3][0]); acc[3][1] = fmaf(a3, b1, acc[3][1]);
        acc[3][2] = fmaf(a3, b2, acc[3][2]); acc[3][3] = fmaf(a3, b3, acc[3][3]);
    }

    float* out = QPE + ((long)bh * Tn + it * 64) * MAXP;
#pragma unroll
    for (int ii = 0; ii < 4; ii++) {
        float4 o4 = make_float4(acc[ii][0], acc[ii][1], acc[ii][2], acc[ii][3]);
        *(float4*)(out + (long)(ty * 4 + ii) * MAXP + tx * 4) = o4;
    }
}

// ---------------- CoPE: gates + suffix-cumsum + interp + softmax -> bf16 hi/lo probs ------
__global__ __launch_bounds__(256) void cope_kernel(const float* __restrict__ S,
                                                   const float* __restrict__ QPE,
                                                   __nv_bfloat16* __restrict__ Ph,
                                                   __nv_bfloat16* __restrict__ Pl)
{
    const int i = blockIdx.x, bh = blockIdx.y;
    const float* row = S + ((long)bh * Tn + i) * Tn;
    const long prow = ((long)bh * Tn + i) * Tn;
    const float* qpe = QPE + ((long)bh * Tn + i) * MAXP;
    const int blockend = ((i >> 7) + 1) << 7;

    __shared__ float qpes[64];
    __shared__ float wred[8];
    __shared__ float wred2[8];

    const int tid = threadIdx.x, lane = tid & 31, wid = tid >> 5;
    if (tid < 64) qpes[tid] = qpe[tid];

    const int j0 = tid << 2;
    float qk[4] = {0.f, 0.f, 0.f, 0.f};
    if (j0 <= i) {
        float4 s4 = *(const float4*)(row + j0);
        qk[0] = s4.x; qk[1] = s4.y; qk[2] = s4.z; qk[3] = s4.w;
    }

    float lpre[4];
    float run = 0.f;
#pragma unroll
    for (int q = 0; q < 4; q++) {
        float gg = 0.f;
        if (j0 + q <= i)
            gg = __fdividef(1.f, 1.f + __expf(-0.125f * qk[q]));
        run += gg;
        lpre[q] = run;
    }

    float v = run;
#pragma unroll
    for (int o = 1; o < 32; o <<= 1) {
        float t = __shfl_up_sync(0xffffffffu, v, o);
        if (lane >= o) v += t;
    }
    if (lane == 31) wred[wid] = v;
    __syncthreads();
    if (tid < 8) {
        float w = wred[tid];
#pragma unroll
        for (int o = 1; o < 8; o <<= 1) {
            float t = __shfl_up_sync(0x000000ffu, w, o);
            if (tid >= o) w += t;
        }
        wred[tid] = w;
    }
    __syncthreads();
    const float base  = (v - run) + (wid ? wred[wid - 1] : 0.f);
    const float total = wred[7];

    float sc[4];
    float mx = -INFINITY;
#pragma unroll
    for (int q = 0; q < 4; q++) {
        float s_ = -INFINITY;
        if (j0 + q <= i) {
            float pos = total - (base + lpre[q]);
            pos = fminf(fmaxf(pos, 0.f), 63.f);
            float pf = floorf(pos);
            int fi = (int)pf;
            float al = pos - pf;
            int ci = (fi < 63) ? fi + 1 : 63;
            float qf = qpes[fi], qc = qpes[ci];
            float qv = qf + al * (qc - qf);
            s_ = 0.125f * (qk[q] + qv);
        }
        sc[q] = s_;
        mx = fmaxf(mx, s_);
    }
#pragma unroll
    for (int o = 16; o; o >>= 1) mx = fmaxf(mx, __shfl_xor_sync(0xffffffffu, mx, o));
    if (lane == 0) wred2[wid] = mx;
    __syncthreads();
    float bmax = wred2[0];
#pragma unroll
    for (int k = 1; k < 8; k++) bmax = fmaxf(bmax, wred2[k]);

    float p[4];
    float ssum = 0.f;
#pragma unroll
    for (int q = 0; q < 4; q++) {
        float e = (j0 + q <= i) ? __expf(sc[q] - bmax) : 0.f;
        p[q] = e;
        ssum += e;
    }
#pragma unroll
    for (int o = 16; o; o >>= 1) ssum += __shfl_xor_sync(0xffffffffu, ssum, o);
    __syncthreads();
    if (lane == 0) wred2[wid] = ssum;
    __syncthreads();
    float tot = 0.f;
#pragma unroll
    for (int k = 0; k < 8; k++) tot += wred2[k];
    const float inv = __fdividef(1.f, tot);

    if (j0 < blockend) {
        float v0 = p[0] * inv, v1 = p[1] * inv, v2 = p[2] * inv, v3 = p[3] * inv;
        __nv_bfloat16 h0 = __float2bfloat16(v0), h1 = __float2bfloat16(v1);
        __nv_bfloat16 h2 = __float2bfloat16(v2), h3 = __float2bfloat16(v3);
        __nv_bfloat162 H0; H0.x = h0; H0.y = h1;
        __nv_bfloat162 H1; H1.x = h2; H1.y = h3;
        __nv_bfloat162 L0, L1;
        L0.x = __float2bfloat16(v0 - __bfloat162float(h0));
        L0.y = __float2bfloat16(v1 - __bfloat162float(h1));
        L1.x = __float2bfloat16(v2 - __bfloat162float(h2));
        L1.y = __float2bfloat16(v3 - __bfloat162float(h3));
        *(__nv_bfloat162*)(Ph + prow + j0)     = H0;
        *(__nv_bfloat162*)(Ph + prow + j0 + 2) = H1;
        *(__nv_bfloat162*)(Pl + prow + j0)     = L0;
        *(__nv_bfloat162*)(Pl + prow + j0 + 2) = L1;
    }
}

// ---------------- pv HMMA: AO = P @ V ----------------
#define PPITCH 144
#define PMATB (128*PPITCH)
#define VMATB (64*PPITCH)
#define PVSTG (2*PMATB + 2*VMATB)
#define PV_SMEM (2*PVSTG)

__global__ __launch_bounds__(256, 1) void pv_hmma(
    const __nv_bfloat16* __restrict__ Ph, const __nv_bfloat16* __restrict__ Pl,
    const __nv_bfloat16* __restrict__ Vth, const __nv_bfloat16* __restrict__ Vtl,
    __nv_bfloat16* __restrict__ AOh, __nv_bfloat16* __restrict__ AOl)
{
    extern __shared__ char dsm[];
    const uint32_t sbase = smem_u32(dsm);

    const int tid  = threadIdx.x;
    const int wid  = tid >> 5;
    const int lane = tid & 31;
    const int wm   = wid & 1;
    const int wn   = wid >> 1;
    const int it   = blockIdx.x;
    const int bh   = blockIdx.y;
    const int b    = bh >> 4, h = bh & 15;

    const __nv_bfloat16* Pr_h = Ph + ((long)bh * Tn + it * 128) * Tn;
    const __nv_bfloat16* Pr_l = Pl + ((long)bh * Tn + it * 128) * Tn;
    const __nv_bfloat16* Vh_  = Vth + (long)bh * DHn * Tn;
    const __nv_bfloat16* Vl_  = Vtl + (long)bh * DHn * Tn;

    float acc[4][2][4];
#pragma unroll
    for (int i = 0; i < 4; i++)
#pragma unroll
        for (int j = 0; j < 2; j++)
#pragma unroll
            for (int c = 0; c < 4; c++) acc[i][j][c] = 0.f;

    const int KS = 2 * (it + 1);

    auto load_stage = [&](int slot, int ks) {
        const uint32_t base = sbase + slot * PVSTG;
        const int k0 = ks * 64;
#pragma unroll
        for (int c = tid; c < 1024; c += 256) {
            const int r = c >> 3, seg = c & 7;
            const uint32_t d = base + r * PPITCH + seg * 16;
            const long off = (long)r * Tn + k0 + seg * 8;
            cpa16(d,         Pr_h + off);
            cpa16(d + PMATB, Pr_l + off);
        }
#pragma unroll
        for (int c = tid; c < 512; c += 256) {
            const int r = c >> 3, seg = c & 7;
            const uint32_t d = base + 2*PMATB + r * PPITCH + seg * 16;
            const long off = (long)r * Tn + k0 + seg * 8;
            cpa16(d,         Vh_ + off);
            cpa16(d + VMATB, Vl_ + off);
        }
        CPA_COMMIT();
    };

    load_stage(0, 0);

    const uint32_t a_row = (uint32_t)(wm * 64 + (lane & 15)) * PPITCH;
    const uint32_t b_row = (uint32_t)(wn * 16 + (lane & 15)) * PPITCH;
    const uint32_t lcol  = (uint32_t)((lane >> 4) * 16);

    for (int k = 0; k < KS; k++) {
        if (k + 1 < KS) load_stage((k + 1) & 1, k + 1);
        if (k + 1 < KS) { CPA_WAIT1(); } else { CPA_WAIT0(); }
        __syncthreads();

        const uint32_t st = sbase + (k & 1) * PVSTG;
#pragma unroll
        for (int kc = 0; kc < 4; kc++) {
            const uint32_t col = kc * 32 + lcol;
            uint32_t ah[4][4], al[4][4], bh4[4], bl4[4];
#pragma unroll
            for (int mt = 0; mt < 4; mt++) {
                const uint32_t ad = st + a_row + (uint32_t)(mt * 16 * PPITCH) + col;
                LDSM4(ah[mt], ad);
                LDSM4(al[mt], ad + PMATB);
            }
            {
                const uint32_t bd = st + 2*PMATB + b_row + col;
                LDSM4(bh4, bd);
                LDSM4(bl4, bd + VMATB);
            }
#pragma unroll
            for (int mt = 0; mt < 4; mt++)
#pragma unroll
                for (int nt = 0; nt < 2; nt++) {
                    MMA_BF16(acc[mt][nt], ah[mt], bh4[nt], bh4[nt + 2]);
                    MMA_BF16(acc[mt][nt], ah[mt], bl4[nt], bl4[nt + 2]);
                    MMA_BF16(acc[mt][nt], al[mt], bh4[nt], bh4[nt + 2]);
                }
        }
        __syncthreads();
    }

#pragma unroll
    for (int mt = 0; mt < 4; mt++)
#pragma unroll
        for (int nt = 0; nt < 2; nt++) {
            const int i0 = it * 128 + wm * 64 + mt * 16 + (lane >> 2);
            const int dh = wn * 16 + nt * 8 + (lane & 3) * 2;
#pragma unroll
            for (int half = 0; half < 2; half++) {
                const int t = i0 + half * 8;
                const float v0 = acc[mt][nt][half * 2 + 0];
                const float v1 = acc[mt][nt][half * 2 + 1];
                const long base = ((long)b * Tn + t) * Dm + h * 64 + dh;
                __nv_bfloat16 h0 = __float2bfloat16(v0);
                __nv_bfloat16 h1 = __float2bfloat16(v1);
                __nv_bfloat162 H; H.x = h0; H.y = h1;
                __nv_bfloat162 L;
                L.x = __float2bfloat16(v0 - __bfloat162float(h0));
                L.y = __float2bfloat16(v1 - __bfloat162float(h1));
                *(__nv_bfloat162*)(AOh + base) = H;
                *(__nv_bfloat162*)(AOl + base) = L;
            }
        }
}

// ---------------- launcher ----------------
extern "C" void kernel_launch(void* const* d_in, const int* in_sizes, int n_in,
                              void* d_out, int out_size)
{
    (void)in_sizes; (void)n_in; (void)out_size;
    const float* x  = (const float*)d_in[0];
    const float* Wq = (const float*)d_in[1];
    const float* bq = (const float*)d_in[2];
    const float* Wk = (const float*)d_in[3];
    const float* bk = (const float*)d_in[4];
    const float* Wv = (const float*)d_in[5];
    const float* bv = (const float*)d_in[6];
    const float* Wo = (const float*)d_in[7];
    const float* bo = (const float*)d_in[8];
    const float* pe = (const float*)d_in[9];
    float* out = (float*)d_out;

    float *Qf, *QPEd, *Sd;
    __nv_bfloat16 *xh, *xl, *Wqh, *Wql, *Wkh, *Wkl, *Wvh, *Wvl, *Woh, *Wol;
    __nv_bfloat16 *Qh, *Ql, *Kh, *Kl, *AOh, *AOl, *Phd, *Pld, *Vth, *Vtl;
    cudaGetSymbolAddress((void**)&Qf, g_Qf);
    cudaGetSymbolAddress((void**)&QPEd, g_QPE);
    cudaGetSymbolAddress((void**)&Sd, g_S);
    cudaGetSymbolAddress((void**)&xh, g_xh);   cudaGetSymbolAddress((void**)&xl, g_xl);
    cudaGetSymbolAddress((void**)&Wqh, g_Wqh); cudaGetSymbolAddress((void**)&Wql, g_Wql);
    cudaGetSymbolAddress((void**)&Wkh, g_Wkh); cudaGetSymbolAddress((void**)&Wkl, g_Wkl);
    cudaGetSymbolAddress((void**)&Wvh, g_Wvh); cudaGetSymbolAddress((void**)&Wvl, g_Wvl);
    cudaGetSymbolAddress((void**)&Woh, g_Woh); cudaGetSymbolAddress((void**)&Wol, g_Wol);
    cudaGetSymbolAddress((void**)&Qh, g_Qh);   cudaGetSymbolAddress((void**)&Ql, g_Ql);
    cudaGetSymbolAddress((void**)&Kh, g_Kh);   cudaGetSymbolAddress((void**)&Kl, g_Kl);
    cudaGetSymbolAddress((void**)&AOh, g_AOh); cudaGetSymbolAddress((void**)&AOl, g_AOl);
    cudaGetSymbolAddress((void**)&Phd, g_Ph);  cudaGetSymbolAddress((void**)&Pld, g_Pl);
    cudaGetSymbolAddress((void**)&Vth, g_Vth); cudaGetSymbolAddress((void**)&Vtl, g_Vtl);

    static int smem_set = 0;
    if (!smem_set) {
        cudaFuncSetAttribute(mm_hmma, cudaFuncAttributeMaxDynamicSharedMemorySize, MM_SMEM);
        cudaFuncSetAttribute(qkv_hmma, cudaFuncAttributeMaxDynamicSharedMemorySize, MM_SMEM);
        cudaFuncSetAttribute(pv_hmma, cudaFuncAttributeMaxDynamicSharedMemorySize, PV_SMEM);
        smem_set = 1;
    }

    dim3 blk(256);

    // splits (kept as 5 launches so ncu -s 5 captures qkv_hmma next)
    splitk<<<2048, blk>>>(x, xh, xl, Bsz * Tn * Dm);
    splitk<<<1024, blk>>>(Wq, Wqh, Wql, Dm * Dm);
    splitk<<<1024, blk>>>(Wk, Wkh, Wkl, Dm * Dm);
    splitk<<<1024, blk>>>(Wv, Wvh, Wvl, Dm * Dm);
    splitk<<<1024, blk>>>(Wo, Woh, Wol, Dm * Dm);

    // merged QKV projection (z selects Q/K/V); V written directly transposed
    qkv_hmma<<<dim3(8, 16, 3), blk, MM_SMEM>>>(xh, xl, Wqh, Wql, Wkh, Wkl, Wvh, Wvl,
                                               bq, bk, bv, Qf, Qh, Ql, Kh, Kl, Vth, Vtl);

    // qk = Q @ K^T per (b,h), causal tile skip
    mm_hmma<<<dim3(8, 8, 32), blk, MM_SMEM>>>(Qh, Ql, Kh, Kl, nullptr,
                                              Sd, 1024, 1024, 64,
                                              (long)Tn * DHn, (long)Tn * DHn, (long)Tn * Tn, 1);

    qpe_kernel<<<dim3(16, 32), blk>>>(pe, Qf, QPEd);

    cope_kernel<<<dim3(1024, 32), blk>>>(Sd, QPEd, Phd, Pld);

    pv_hmma<<<dim3(8, 32), blk, PV_SMEM>>>(Phd, Pld, Vth, Vtl, AOh, AOl);

    // output projection (z=0)
    mm_hmma<<<dim3(8, 16, 1), blk, MM_SMEM>>>(AOh, AOl, Woh, Wol, bo,
                                              out, 2048, 1024, 1024, 0, 0, 0, 0);
}